// round 9
// baseline (speedup 1.0000x reference)
#include <cuda_runtime.h>
#include <cuda_bf16.h>
#include <math.h>

// Problem dims
#define TT 512
#define BB 64
#define II 512
#define HH 512

// ---------------- device scratch ----------------
__device__ float g_xz[TT * BB];   // [t][b] includes zt_w_b
__device__ float g_xr[TT * BB];   // [t][b] includes rt_w_b

// ---------------- helpers ----------------
typedef unsigned long long ull;
union U64F2 { ull u; float2 f; };
union QU    { uint4 q; ull u[2]; };

__device__ __forceinline__ void fma2(ull& d, ull a, ull b) {
    asm("fma.rn.f32x2 %0, %1, %2, %0;" : "+l"(d) : "l"(a), "l"(b));
}
__device__ __forceinline__ ull pack2(float lo, float hi) {
    ull r; asm("mov.b64 %0, {%1, %2};" : "=l"(r) : "f"(lo), "f"(hi)); return r;
}
__device__ __forceinline__ float sigmoid_fast(float x) {
    float e, r;
    asm("ex2.approx.f32 %0, %1;" : "=f"(e) : "f"(-1.4426950408889634f * x));
    asm("rcp.approx.f32 %0, %1;" : "=f"(r) : "f"(1.0f + e));
    return r;
}
__device__ __forceinline__ float tanh_fast(float x) {
    float e, r;
    asm("ex2.approx.f32 %0, %1;" : "=f"(e) : "f"(-2.8853900817779268f * x));
    asm("rcp.approx.f32 %0, %1;" : "=f"(r) : "f"(1.0f + e));
    return fmaf(2.0f, r, -1.0f);
}
__device__ __forceinline__ unsigned smem_u32(const void* p) {
    return (unsigned)__cvta_generic_to_shared(p);
}

// ---------------- kernel 1: gate input projections xz, xr ----------------
__global__ void gate_pre_kernel(const float* __restrict__ in,
                                const float* __restrict__ zw, const float* __restrict__ zb,
                                const float* __restrict__ rw, const float* __restrict__ rb) {
    int row  = blockIdx.x * 8 + (threadIdx.x >> 5);
    int lane = threadIdx.x & 31;
    const float4* a4 = (const float4*)(in + (size_t)row * II);
    const float4* z4 = (const float4*)zw;
    const float4* r4 = (const float4*)rw;
    float az = 0.f, ar = 0.f;
#pragma unroll 4
    for (int i = lane; i < II / 4; i += 32) {
        float4 v = a4[i];
        float4 z = z4[i];
        float4 r = r4[i];
        az += v.x * z.x + v.y * z.y + v.z * z.z + v.w * z.w;
        ar += v.x * r.x + v.y * r.y + v.z * r.z + v.w * r.w;
    }
#pragma unroll
    for (int off = 16; off >= 1; off >>= 1) {
        az += __shfl_xor_sync(0xffffffffu, az, off);
        ar += __shfl_xor_sync(0xffffffffu, ar, off);
    }
    if (lane == 0) {
        g_xz[row] = az + zb[0];
        g_xr[row] = ar + rb[0];
    }
}

// ---------------- kernel 2: xn GEMM (R6, proven) ----------------
__global__ __launch_bounds__(256) void xn_gemm_kernel(const float* __restrict__ A,
                                                      const float* __restrict__ W,
                                                      const float* __restrict__ bias,
                                                      float* __restrict__ C) {
    __shared__ ull As2[16][130];
    __shared__ ull Ws2[16][66];

    int tid  = threadIdx.x;
    int ncol = tid & 7;
    int mrow = tid >> 3;
    int nc2  = ncol * 2;
    int bm   = blockIdx.x * 128;
    int bn   = blockIdx.y * 64;

    ull acc[4][8];
#pragma unroll
    for (int i = 0; i < 4; i++)
#pragma unroll
        for (int j = 0; j < 8; j++) acc[i][j] = 0ull;

    const float4* A4 = (const float4*)A;
    const float4* W4 = (const float4*)W;

    float4 pa[4], pw[2];
#pragma unroll
    for (int q = 0; q < 4; q++) {
        int s = tid + q * 256;
        pa[q] = A4[(size_t)(bm + (s >> 3)) * 128 + (s & 7)];
    }
#pragma unroll
    for (int q = 0; q < 2; q++) {
        int s = tid + q * 256;
        pw[q] = W4[(size_t)(bn + (s >> 3)) * 128 + (s & 7)];
    }

    for (int blk = 0; blk < 16; blk++) {
#pragma unroll
        for (int q = 0; q < 4; q++) {
            int s = tid + q * 256;
            int m = s >> 3, f4 = s & 7;
            As2[f4 * 2][m]     = pack2(pa[q].x, pa[q].y);
            As2[f4 * 2 + 1][m] = pack2(pa[q].z, pa[q].w);
        }
#pragma unroll
        for (int q = 0; q < 2; q++) {
            int s = tid + q * 256;
            int n = s >> 3, f4 = s & 7;
            Ws2[f4 * 2][n]     = pack2(pw[q].x, pw[q].y);
            Ws2[f4 * 2 + 1][n] = pack2(pw[q].z, pw[q].w);
        }
        __syncthreads();
        if (blk < 15) {
            int kq = (blk + 1) * 8;
#pragma unroll
            for (int q = 0; q < 4; q++) {
                int s = tid + q * 256;
                pa[q] = A4[(size_t)(bm + (s >> 3)) * 128 + kq + (s & 7)];
            }
#pragma unroll
            for (int q = 0; q < 2; q++) {
                int s = tid + q * 256;
                pw[q] = W4[(size_t)(bn + (s >> 3)) * 128 + kq + (s & 7)];
            }
        }
#pragma unroll
        for (int kp = 0; kp < 16; kp++) {
            QU a01, a23, w0, w1, w2, w3;
            a01.q = *(const uint4*)&As2[kp][mrow * 4];
            a23.q = *(const uint4*)&As2[kp][mrow * 4 + 2];
            w0.q  = *(const uint4*)&Ws2[kp][nc2];
            w1.q  = *(const uint4*)&Ws2[kp][nc2 + 16];
            w2.q  = *(const uint4*)&Ws2[kp][nc2 + 32];
            w3.q  = *(const uint4*)&Ws2[kp][nc2 + 48];
            ull av[4] = {a01.u[0], a01.u[1], a23.u[0], a23.u[1]};
            ull wv[8] = {w0.u[0], w0.u[1], w1.u[0], w1.u[1],
                         w2.u[0], w2.u[1], w3.u[0], w3.u[1]};
#pragma unroll
            for (int i = 0; i < 4; i++)
#pragma unroll
                for (int j = 0; j < 8; j++) fma2(acc[i][j], av[i], wv[j]);
        }
        __syncthreads();
    }

    float2 bq[4];
#pragma unroll
    for (int q = 0; q < 4; q++)
        bq[q] = ((const float2*)bias)[(bn >> 1) + (nc2 >> 1) + q * 8];

#pragma unroll
    for (int mi = 0; mi < 4; mi++) {
        int m = bm + mrow * 4 + mi;
#pragma unroll
        for (int q = 0; q < 4; q++) {
            U64F2 c0, c1;
            c0.u = acc[mi][q * 2];
            c1.u = acc[mi][q * 2 + 1];
            float2 o;
            o.x = c0.f.x + c0.f.y + bq[q].x;
            o.y = c1.f.x + c1.f.y + bq[q].y;
            ((float2*)C)[(size_t)m * 256 + (bn >> 1) + (nc2 >> 1) + q * 8] = o;
        }
    }
}

// ---------------- kernel 3: recurrent scan, PARTIAL-EXCHANGE layout -------
// CTA r of each 8-CTA cluster owns k-chunk r (W[:, 64k] = 128KB smem) and
// jj-chunk r. Per step: reduce 8 incoming partial msgs -> h_new (own chunk
// only, = own k-slice!) -> dot produces 8 outgoing 1KB partials, sent per
// warp-pair via cp.async.bulk as soon as ready. Gate partials: 32B msgs.
#define W_OFF    0                         // float[512jj][64k] packed = 128KB
#define RB_OFF   131072                    // rbuf: 2 x 8 x 1056B = 16896
#define HL_OFF   (RB_OFF + 16896)          // hL: ull[32kp][4b] = 1024
#define PART_OFF (HL_OFF + 1024)           // part: 8x32x8 floats = 8192
#define SB_OFF   (PART_OFF + 8192)         // sbuf: 2 x 8 x 1024B = 16384
#define GS_OFF   (SB_OFF + 16384)          // gsbuf: 2 x 8 x 32B = 512
#define GP_OFF   (GS_OFF + 512)            // gpart: 16 floats = 64
#define MB_OFF   (GP_OFF + 64)             // 2 x b64
#define SC_SMEM  (MB_OFF + 64)

extern __shared__ char sc_smem[];

__global__ void __cluster_dims__(8, 1, 1) __launch_bounds__(512, 1)
scan_kernel(const float* __restrict__ hidden,
            const float* __restrict__ ztu_g, const float* __restrict__ ztub,
            const float* __restrict__ rtu_g, const float* __restrict__ rtub,
            const float* __restrict__ huw, const float* __restrict__ hub_g,
            float* __restrict__ out, int tail) {
    float* wS    = (float*)(sc_smem + W_OFF);
    float* rbuf  = (float*)(sc_smem + RB_OFF);   // [2][8][264 floats]
    ull*   hL    = (ull*)(sc_smem + HL_OFF);     // [kp*4+b]
    float* part  = (float*)(sc_smem + PART_OFF);
    float* sbuf  = (float*)(sc_smem + SB_OFF);   // [2][8][256 floats]
    float* gsbuf = (float*)(sc_smem + GS_OFF);   // [2][8][8 floats]
    float* gpart = (float*)(sc_smem + GP_OFF);   // [8 warps][2 gates]

    int tid    = threadIdx.x;
    int rank   = blockIdx.x & 7;
    int grp    = blockIdx.x >> 3;
    int jjbase = rank * 64;
    unsigned mbase = smem_u32(sc_smem + MB_OFF);

    int lane  = tid & 31;
    int warp  = tid >> 5;
    int pairq = warp >> 1;     // chunk this pair computes (0..7)
    int ksw   = warp & 1;      // kp half: [16ksw, 16ksw+16)
    int jjp   = lane;          // jj-pair within chunk (0..31)
    int jj4   = tid & 63;      // Phase A: jj within own chunk
    int b4    = (tid >> 6) & 3;

    // -------- prologue: weights W[:, own k-chunk] packed for the dot ------
    // wS uint4 entry (q*32+kp)*32+jjp = {w[jj0][k0],w[jj0][k1],w[jj1][k0],w[jj1][k1]}
    for (int i = tid; i < 512 * 64; i += 512) {
        int jj = i >> 6, kl = i & 63;
        int q = jj >> 6, jp = (jj >> 1) & 31, half = jj & 1;
        int kp = kl >> 1, ko = kl & 1;
        wS[((q * 32 + kp) * 32 + jp) * 4 + half * 2 + ko] =
            huw[(size_t)jj * HH + jjbase + kl];
    }
    // h(0) own k-chunk into hL
    if (tid < 128) {
        int kp = tid >> 2, b = tid & 3;
        hL[tid] = ((const ull*)(hidden + (size_t)(grp * 4 + b) * HH + jjbase))[kp];
    }
    if (tid == 0) {
        asm volatile("mbarrier.init.shared.b64 [%0], %1;" :: "r"(mbase), "r"(1) : "memory");
        asm volatile("mbarrier.init.shared.b64 [%0], %1;" :: "r"(mbase + 8), "r"(1) : "memory");
        asm volatile("mbarrier.arrive.expect_tx.shared::cta.b64 _, [%0], %1;"
                     :: "r"(mbase), "r"(8448) : "memory");
        asm volatile("mbarrier.arrive.expect_tx.shared::cta.b64 _, [%0], %1;"
                     :: "r"(mbase + 8), "r"(8448) : "memory");
    }

    float zub = ztub[0], rub = rtub[0];
    float hubv = 0.f, uzfv = 0.f, urfv = 0.f;
    if (tid < 256) {
        hubv = hub_g[jjbase + jj4];
        uzfv = ztu_g[jjbase + jj4];   // gate u over own k-chunk (k == jjbase+jj4)
        urfv = rtu_g[jjbase + jj4];
    }

    // remote targets
    unsigned dst_pair = 0, mb_pair = 0;      // lane0 of ks0 warp: pair send
    if (ksw == 0 && lane == 0) {
        unsigned loc = smem_u32(rbuf);
        unsigned rem;
        asm("mapa.shared::cluster.u32 %0, %1, %2;" : "=r"(rem) : "r"(loc), "r"(pairq));
        dst_pair = rem + (unsigned)rank * 1056u;
        asm("mapa.shared::cluster.u32 %0, %1, %2;" : "=r"(mb_pair) : "r"(mbase), "r"(pairq));
    }
    unsigned dst_gate = 0, mb_gate = 0;      // tid<8: gate send to CTA tid
    if (tid < 8) {
        unsigned loc = smem_u32(rbuf);
        unsigned rem;
        asm("mapa.shared::cluster.u32 %0, %1, %2;" : "=r"(rem) : "r"(loc), "r"(tid));
        dst_gate = rem + (unsigned)rank * 1056u + 1024u;
        asm("mapa.shared::cluster.u32 %0, %1, %2;" : "=r"(mb_gate) : "r"(mbase), "r"(tid));
    }

    // step-0 input prefetch + prologue gate partials (u . h(0) own chunk)
    size_t obase = 0;
    float xnv = 0.f, xzv = 0.f, xrv = 0.f;
    if (tid < 256) {
        obase = (size_t)(grp * 4 + b4) * HH + jjbase + jj4;
        xnv = out[obase];
        xzv = g_xz[grp * 4 + b4];
        xrv = g_xr[grp * 4 + b4];
        float h0 = hidden[(size_t)(grp * 4 + b4) * HH + jjbase + jj4];
        float pz = uzfv * h0, pr = urfv * h0;
#pragma unroll
        for (int off = 16; off >= 1; off >>= 1) {
            pz += __shfl_xor_sync(0xffffffffu, pz, off);
            pr += __shfl_xor_sync(0xffffffffu, pr, off);
        }
        if (lane == 0) { gpart[warp * 2] = pz; gpart[warp * 2 + 1] = pr; }
    }
    __syncthreads();
    asm volatile("barrier.cluster.arrive.aligned;" ::: "memory");
    asm volatile("barrier.cluster.wait.aligned;" ::: "memory");

    int p0 = 0, p1 = 0;

    for (int t = -1; t < TT; t++) {
        // ---------------- Phase A (t >= 0) ----------------
        if (t >= 0) {
            int s = t & 1;
            if (tid == 0) {
                int ph = s ? p1 : p0;
                unsigned done = 0;
                while (!done) {
                    asm volatile(
                        "{\n\t.reg .pred p;\n\t"
                        "mbarrier.try_wait.parity.acquire.cta.shared::cta.b64 p, [%1], %2, 0x989680;\n\t"
                        "selp.b32 %0, 1, 0, p;\n\t}"
                        : "=r"(done) : "r"(mbase + s * 8), "r"(ph) : "memory");
                }
            }
            if (s) p1 ^= 1; else p0 ^= 1;
            __syncthreads();
            if (tid == 0) {
                asm volatile("mbarrier.arrive.expect_tx.shared::cta.b64 _, [%0], %1;"
                             :: "r"(mbase + s * 8), "r"(8448) : "memory");
            }

            if (tid < 256) {
                const float* rb = rbuf + s * 2112;
                float ssum = 0.f, gz = 0.f, gr = 0.f;
#pragma unroll
                for (int src = 0; src < 8; src++) {
                    const float* m = rb + src * 264;
                    ssum += m[b4 * 64 + jj4];
                    gz   += m[256 + b4];
                    gr   += m[260 + b4];
                }
                float zt = sigmoid_fast(xzv + gz + zub);
                float rt = sigmoid_fast(xrv + gr + rub);
                float nt = tanh_fast(fmaf(ssum + hubv, rt, xnv));
                U64F2 h2; h2.u = hL[(jj4 >> 1) * 4 + b4];
                float hold = (jj4 & 1) ? h2.f.y : h2.f.x;
                float hn = (1.f - zt) * nt + zt * hold;

                out[obase] = hn;
                float hn1 = __shfl_down_sync(0xffffffffu, hn, 1);
                if ((jj4 & 1) == 0) hL[(jj4 >> 1) * 4 + b4] = pack2(hn, hn1);

                // gate partials for NEXT messages: u . h(t+1)[own chunk]
                float pz = uzfv * hn, pr = urfv * hn;
#pragma unroll
                for (int off = 16; off >= 1; off >>= 1) {
                    pz += __shfl_xor_sync(0xffffffffu, pz, off);
                    pr += __shfl_xor_sync(0xffffffffu, pr, off);
                }
                if (lane == 0) { gpart[warp * 2] = pz; gpart[warp * 2 + 1] = pr; }

                if (t < TT - 1) {
                    obase += (size_t)BB * HH;
                    xnv = out[obase];
                    xzv = g_xz[(t + 1) * BB + grp * 4 + b4];
                    xrv = g_xr[(t + 1) * BB + grp * 4 + b4];
                } else if (tail >= BB * HH) {
                    out[(size_t)TT * BB * HH + (size_t)(grp * 4 + b4) * HH + jjbase + jj4] = hn;
                }
            }
            __syncthreads();
        }

        // ---------------- Phase B (t < TT-1): dot + sends ----------------
        if (t < TT - 1) {
            int sf = (t + 1) & 1;

            // gate sends (tid<8 -> CTA tid), ordered by the syncthreads above
            if (tid < 8) {
                float* gs = gsbuf + sf * 64 + tid * 8;
#pragma unroll
                for (int gb = 0; gb < 8; gb++) {
                    int b = gb & 3, g = gb >> 2;
                    gs[gb] = gpart[(b * 2) * 2 + g] + gpart[(b * 2 + 1) * 2 + g];
                }
                asm volatile("fence.proxy.async.shared::cta;" ::: "memory");
                asm volatile(
                    "cp.async.bulk.shared::cluster.shared::cta.mbarrier::complete_tx::bytes "
                    "[%0], [%1], %2, [%3];"
                    :: "r"(dst_gate + (unsigned)sf * 8448u), "r"(smem_u32(gs)),
                       "r"(32u), "r"(mb_gate + (unsigned)sf * 8u) : "memory");
            }

            // dot: pair 'pairq' computes chunk pairq over own 64 k
            {
                int kp0 = ksw * 16;
                const uint4* wq4 = ((const uint4*)wS) + (pairq * 32 + kp0) * 32 + jjp;
                const uint4* hq4 = ((const uint4*)hL) + kp0 * 2;
                ull a00 = 0, a01 = 0, a02 = 0, a03 = 0;
                ull a10 = 0, a11 = 0, a12 = 0, a13 = 0;
#pragma unroll
                for (int i = 0; i < 16; i++) {
                    QU Wq, Ha, Hb;
                    Wq.q = wq4[i * 32];
                    Ha.q = hq4[i * 2];
                    Hb.q = hq4[i * 2 + 1];
                    fma2(a00, Wq.u[0], Ha.u[0]);
                    fma2(a01, Wq.u[0], Ha.u[1]);
                    fma2(a02, Wq.u[0], Hb.u[0]);
                    fma2(a03, Wq.u[0], Hb.u[1]);
                    fma2(a10, Wq.u[1], Ha.u[0]);
                    fma2(a11, Wq.u[1], Ha.u[1]);
                    fma2(a12, Wq.u[1], Hb.u[0]);
                    fma2(a13, Wq.u[1], Hb.u[1]);
                }
                U64F2 c;
                float s00, s01, s02, s03, s10, s11, s12, s13;
                c.u = a00; s00 = c.f.x + c.f.y;
                c.u = a01; s01 = c.f.x + c.f.y;
                c.u = a02; s02 = c.f.x + c.f.y;
                c.u = a03; s03 = c.f.x + c.f.y;
                c.u = a10; s10 = c.f.x + c.f.y;
                c.u = a11; s11 = c.f.x + c.f.y;
                c.u = a12; s12 = c.f.x + c.f.y;
                c.u = a13; s13 = c.f.x + c.f.y;

                float* pslot = part + (pairq * 32 + jjp) * 8;
                if (ksw) {
                    ((float4*)pslot)[0] = make_float4(s00, s01, s02, s03);
                    ((float4*)pslot)[1] = make_float4(s10, s11, s12, s13);
                }
                asm volatile("bar.sync %0, %1;" :: "r"(pairq + 1), "r"(64) : "memory");
                if (!ksw) {
                    float4 q0 = ((float4*)pslot)[0];
                    float4 q1 = ((float4*)pslot)[1];
                    s00 += q0.x; s01 += q0.y; s02 += q0.z; s03 += q0.w;
                    s10 += q1.x; s11 += q1.y; s12 += q1.z; s13 += q1.w;
                    float2* sb = (float2*)(sbuf + sf * 2048 + pairq * 256);
                    sb[0 * 32 + jjp] = make_float2(s00, s10);
                    sb[1 * 32 + jjp] = make_float2(s01, s11);
                    sb[2 * 32 + jjp] = make_float2(s02, s12);
                    sb[3 * 32 + jjp] = make_float2(s03, s13);
                    __syncwarp();
                    if (lane == 0) {
                        asm volatile("fence.proxy.async.shared::cta;" ::: "memory");
                        asm volatile(
                            "cp.async.bulk.shared::cluster.shared::cta.mbarrier::complete_tx::bytes "
                            "[%0], [%1], %2, [%3];"
                            :: "r"(dst_pair + (unsigned)sf * 8448u),
                               "r"(smem_u32(sbuf + sf * 2048 + pairq * 256)),
                               "r"(1024u), "r"(mb_pair + (unsigned)sf * 8u) : "memory");
                    }
                }
            }
        }
    }

    // teardown: no CTA leaves while peers may still target its smem
    asm volatile("barrier.cluster.arrive.aligned;" ::: "memory");
    asm volatile("barrier.cluster.wait.aligned;" ::: "memory");
}

// ---------------- launch ----------------
extern "C" void kernel_launch(void* const* d_in, const int* in_sizes, int n_in,
                              void* d_out, int out_size) {
    const float* input  = (const float*)d_in[0];
    const float* hidden = (const float*)d_in[1];
    const float* zt_w_w = (const float*)d_in[2];
    const float* zt_w_b = (const float*)d_in[3];
    const float* zt_u_w = (const float*)d_in[4];
    const float* zt_u_b = (const float*)d_in[5];
    const float* rt_w_w = (const float*)d_in[6];
    const float* rt_w_b = (const float*)d_in[7];
    const float* rt_u_w = (const float*)d_in[8];
    const float* rt_u_b = (const float*)d_in[9];
    const float* h_w_w  = (const float*)d_in[10];
    const float* h_w_b  = (const float*)d_in[11];
    const float* h_u_w  = (const float*)d_in[12];
    const float* h_u_b  = (const float*)d_in[13];
    float* out = (float*)d_out;

    int tail = out_size - TT * BB * HH;

    gate_pre_kernel<<<TT * BB / 8, 256>>>(input, zt_w_w, zt_w_b, rt_w_w, rt_w_b);

    {
        dim3 grid(TT * BB / 128, HH / 64);
        xn_gemm_kernel<<<grid, 256>>>(input, h_w_w, h_w_b, out);
    }

    static int smem_set = 0;
    if (!smem_set) {
        cudaFuncSetAttribute(scan_kernel, cudaFuncAttributeMaxDynamicSharedMemorySize, SC_SMEM);
        smem_set = 1;
    }
    scan_kernel<<<128, 512, SC_SMEM>>>(hidden, zt_u_w, zt_u_b, rt_u_w, rt_u_b,
                                       h_u_w, h_u_b, out, tail);
}

// round 11
// speedup vs baseline: 1.6865x; 1.6865x over previous
#include <cuda_runtime.h>
#include <cuda_bf16.h>
#include <math.h>

// Problem dims
#define TT 512
#define BB 64
#define II 512
#define HH 512

// ---------------- device scratch ----------------
__device__ float g_xz[TT * BB];   // [t][b] includes zt_w_b
__device__ float g_xr[TT * BB];   // [t][b] includes rt_w_b

// ---------------- helpers ----------------
typedef unsigned long long ull;
union U64F2 { ull u; float2 f; };
union QU    { uint4 q; ull u[2]; };

__device__ __forceinline__ void fma2(ull& d, ull a, ull b) {
    asm("fma.rn.f32x2 %0, %1, %2, %0;" : "+l"(d) : "l"(a), "l"(b));
}
__device__ __forceinline__ ull pack2(float lo, float hi) {
    ull r; asm("mov.b64 %0, {%1, %2};" : "=l"(r) : "f"(lo), "f"(hi)); return r;
}
__device__ __forceinline__ float sigmoid_fast(float x) {
    float e, r;
    asm("ex2.approx.f32 %0, %1;" : "=f"(e) : "f"(-1.4426950408889634f * x));
    asm("rcp.approx.f32 %0, %1;" : "=f"(r) : "f"(1.0f + e));
    return r;
}
__device__ __forceinline__ float tanh_fast(float x) {
    float e, r;
    asm("ex2.approx.f32 %0, %1;" : "=f"(e) : "f"(-2.8853900817779268f * x));
    asm("rcp.approx.f32 %0, %1;" : "=f"(r) : "f"(1.0f + e));
    return fmaf(2.0f, r, -1.0f);
}
__device__ __forceinline__ unsigned smem_u32(const void* p) {
    return (unsigned)__cvta_generic_to_shared(p);
}

// ---------------- kernel 1: gate input projections xz, xr ----------------
__global__ void gate_pre_kernel(const float* __restrict__ in,
                                const float* __restrict__ zw, const float* __restrict__ zb,
                                const float* __restrict__ rw, const float* __restrict__ rb) {
    int row  = blockIdx.x * 8 + (threadIdx.x >> 5);
    int lane = threadIdx.x & 31;
    const float4* a4 = (const float4*)(in + (size_t)row * II);
    const float4* z4 = (const float4*)zw;
    const float4* r4 = (const float4*)rw;
    float az = 0.f, ar = 0.f;
#pragma unroll 4
    for (int i = lane; i < II / 4; i += 32) {
        float4 v = a4[i];
        float4 z = z4[i];
        float4 r = r4[i];
        az += v.x * z.x + v.y * z.y + v.z * z.z + v.w * z.w;
        ar += v.x * r.x + v.y * r.y + v.z * r.z + v.w * r.w;
    }
#pragma unroll
    for (int off = 16; off >= 1; off >>= 1) {
        az += __shfl_xor_sync(0xffffffffu, az, off);
        ar += __shfl_xor_sync(0xffffffffu, ar, off);
    }
    if (lane == 0) {
        g_xz[row] = az + zb[0];
        g_xr[row] = ar + rb[0];
    }
}

// ---------------- kernel 2: xn GEMM (R6, proven) ----------------
__global__ __launch_bounds__(256) void xn_gemm_kernel(const float* __restrict__ A,
                                                      const float* __restrict__ W,
                                                      const float* __restrict__ bias,
                                                      float* __restrict__ C) {
    __shared__ ull As2[16][130];
    __shared__ ull Ws2[16][66];

    int tid  = threadIdx.x;
    int ncol = tid & 7;
    int mrow = tid >> 3;
    int nc2  = ncol * 2;
    int bm   = blockIdx.x * 128;
    int bn   = blockIdx.y * 64;

    ull acc[4][8];
#pragma unroll
    for (int i = 0; i < 4; i++)
#pragma unroll
        for (int j = 0; j < 8; j++) acc[i][j] = 0ull;

    const float4* A4 = (const float4*)A;
    const float4* W4 = (const float4*)W;

    float4 pa[4], pw[2];
#pragma unroll
    for (int q = 0; q < 4; q++) {
        int s = tid + q * 256;
        pa[q] = A4[(size_t)(bm + (s >> 3)) * 128 + (s & 7)];
    }
#pragma unroll
    for (int q = 0; q < 2; q++) {
        int s = tid + q * 256;
        pw[q] = W4[(size_t)(bn + (s >> 3)) * 128 + (s & 7)];
    }

    for (int blk = 0; blk < 16; blk++) {
#pragma unroll
        for (int q = 0; q < 4; q++) {
            int s = tid + q * 256;
            int m = s >> 3, f4 = s & 7;
            As2[f4 * 2][m]     = pack2(pa[q].x, pa[q].y);
            As2[f4 * 2 + 1][m] = pack2(pa[q].z, pa[q].w);
        }
#pragma unroll
        for (int q = 0; q < 2; q++) {
            int s = tid + q * 256;
            int n = s >> 3, f4 = s & 7;
            Ws2[f4 * 2][n]     = pack2(pw[q].x, pw[q].y);
            Ws2[f4 * 2 + 1][n] = pack2(pw[q].z, pw[q].w);
        }
        __syncthreads();
        if (blk < 15) {
            int kq = (blk + 1) * 8;
#pragma unroll
            for (int q = 0; q < 4; q++) {
                int s = tid + q * 256;
                pa[q] = A4[(size_t)(bm + (s >> 3)) * 128 + kq + (s & 7)];
            }
#pragma unroll
            for (int q = 0; q < 2; q++) {
                int s = tid + q * 256;
                pw[q] = W4[(size_t)(bn + (s >> 3)) * 128 + kq + (s & 7)];
            }
        }
#pragma unroll
        for (int kp = 0; kp < 16; kp++) {
            QU a01, a23, w0, w1, w2, w3;
            a01.q = *(const uint4*)&As2[kp][mrow * 4];
            a23.q = *(const uint4*)&As2[kp][mrow * 4 + 2];
            w0.q  = *(const uint4*)&Ws2[kp][nc2];
            w1.q  = *(const uint4*)&Ws2[kp][nc2 + 16];
            w2.q  = *(const uint4*)&Ws2[kp][nc2 + 32];
            w3.q  = *(const uint4*)&Ws2[kp][nc2 + 48];
            ull av[4] = {a01.u[0], a01.u[1], a23.u[0], a23.u[1]};
            ull wv[8] = {w0.u[0], w0.u[1], w1.u[0], w1.u[1],
                         w2.u[0], w2.u[1], w3.u[0], w3.u[1]};
#pragma unroll
            for (int i = 0; i < 4; i++)
#pragma unroll
                for (int j = 0; j < 8; j++) fma2(acc[i][j], av[i], wv[j]);
        }
        __syncthreads();
    }

    float2 bq[4];
#pragma unroll
    for (int q = 0; q < 4; q++)
        bq[q] = ((const float2*)bias)[(bn >> 1) + (nc2 >> 1) + q * 8];

#pragma unroll
    for (int mi = 0; mi < 4; mi++) {
        int m = bm + mrow * 4 + mi;
#pragma unroll
        for (int q = 0; q < 4; q++) {
            U64F2 c0, c1;
            c0.u = acc[mi][q * 2];
            c1.u = acc[mi][q * 2 + 1];
            float2 o;
            o.x = c0.f.x + c0.f.y + bq[q].x;
            o.y = c1.f.x + c1.f.y + bq[q].y;
            ((float2*)C)[(size_t)m * 256 + (bn >> 1) + (nc2 >> 1) + q * 8] = o;
        }
    }
}

// ---------------- kernel 3: recurrent scan (R6 + per-chunk mbarriers) ----
// 16 clusters x 8 CTAs x 512 threads. Warp w consumes ONLY h-chunk w>>1
// (both its gate k-range and dot k-segment), so each incoming 1KB message
// completes its own mbarrier and each warp waits just for its chunk.
// Own chunk is written locally (no self-message; 7 sends/step).
#define WS_OFF   0                        // ull[256][64]  = 128KB
#define HP_OFF   131072                   // ull[2][1024]  = 16KB
#define PART_OFF (HP_OFF + 16384)         // float[16][4][64] = 16KB
#define ZRP_OFF  (PART_OFF + 16384)       // float[64]
#define ZUP_OFF  (ZRP_OFF + 256)          // ull[256]
#define RUP_OFF  (ZUP_OFF + 2048)         // ull[256]
#define HUB_OFF  (RUP_OFF + 2048)         // float[64]
#define MBAR_OFF (HUB_OFF + 256)          // 16 x b64 = [chunk c][buf s]
#define SC_SMEM  (MBAR_OFF + 128)

extern __shared__ char sc_smem[];

__global__ void __cluster_dims__(8, 1, 1) __launch_bounds__(512, 1)
scan_kernel(const float* __restrict__ hidden,
            const float* __restrict__ ztu_g, const float* __restrict__ ztub,
            const float* __restrict__ rtu_g, const float* __restrict__ rtub,
            const float* __restrict__ huw, const float* __restrict__ hub_g,
            float* __restrict__ out, int tail) {
    ull*   wS   = (ull*)(sc_smem + WS_OFF);
    ull*   hpb  = (ull*)(sc_smem + HP_OFF);
    float* part = (float*)(sc_smem + PART_OFF);
    float* zrpf = (float*)(sc_smem + ZRP_OFF);
    ull*   zup  = (ull*)(sc_smem + ZUP_OFF);
    ull*   rup  = (ull*)(sc_smem + RUP_OFF);
    float* hub  = (float*)(sc_smem + HUB_OFF);

    int tid    = threadIdx.x;
    int rank   = blockIdx.x & 7;
    int grp    = blockIdx.x >> 3;
    int jjbase = rank * 64;
    unsigned mbase = smem_u32(sc_smem + MBAR_OFF);
    unsigned hpb_a = smem_u32(hpb);

    int lane = tid & 31;
    int warp = tid >> 5;
    int jjp  = lane;            // jj pair 0..31
    int ks   = warp;            // k segment 0..15 (16 kp each)
    int gate = warp & 1;
    int ks8  = warp >> 1;
    int chnk = warp >> 1;       // the ONLY h-chunk this warp reads
    int own  = (chnk == rank);
    int jj4  = tid & 63;
    int b4   = (tid >> 6) & 3;

    // -------- prologue --------
    for (int i = tid; i < 64 * 512; i += 512) {
        int jj = i >> 9, k = i & 511;
        ((float*)wS)[((k >> 1) * 64 + jj) * 2 + (k & 1)] = huw[(size_t)(jjbase + jj) * HH + k];
    }
    if (tid < 256) zup[tid] = ((const ull*)ztu_g)[tid];
    else           rup[tid - 256] = ((const ull*)rtu_g)[tid - 256];
    for (int i = tid; i < 1024; i += 512) {
        hpb[i] = ((const ull*)hidden)[(size_t)(grp * 4 + (i & 3)) * 256 + (i >> 2)];
    }
    if (tid < 64) hub[tid] = hub_g[jjbase + tid];
    float zub = ztub[0], rub = rtub[0];
    if (tid == 0) {
#pragma unroll
        for (int m = 0; m < 16; m++) {
            asm volatile("mbarrier.init.shared.b64 [%0], %1;"
                         :: "r"(mbase + m * 8), "r"(1) : "memory");
        }
#pragma unroll
        for (int m = 0; m < 16; m++) {
            asm volatile("mbarrier.arrive.expect_tx.shared::cta.b64 _, [%0], %1;"
                         :: "r"(mbase + m * 8), "r"(1024) : "memory");
        }
    }

    // per-lane remote targets (lanes/tids 0..7 -> peer ranks)
    unsigned dst_r = 0, mb_r = 0;
    if (tid < 8) {
        unsigned rem;
        asm("mapa.shared::cluster.u32 %0, %1, %2;" : "=r"(rem) : "r"(hpb_a), "r"(tid));
        dst_r = rem + (unsigned)rank * 1024u;            // our chunk slot in peer
        asm("mapa.shared::cluster.u32 %0, %1, %2;" : "=r"(rem) : "r"(mbase), "r"(tid));
        mb_r = rem + (unsigned)rank * 16u;               // mbarrier[chunk=rank][s]
    }

    // prefetch step-0 inputs
    size_t obase = 0;
    float xnv = 0.f, xzv = 0.f, xrv = 0.f;
    if (tid < 256) {
        obase = (size_t)(grp * 4 + b4) * HH + jjbase + jj4;
        xnv = out[obase];
        xzv = g_xz[grp * 4 + b4];
        xrv = g_xr[grp * 4 + b4];
    }

    __syncthreads();
    // mbarrier inits/arms visible cluster-wide before any remote complete_tx
    asm volatile("barrier.cluster.arrive.aligned;" ::: "memory");
    asm volatile("barrier.cluster.wait.aligned;" ::: "memory");

    int p0 = 0, p1 = 0;           // per-warp parity for its chunk, buffers 0/1
    unsigned mb_c = mbase + (unsigned)chnk * 16u;

    for (int t = 0; t < TT; t++) {
        int s = t & 1, sf = s ^ 1;

        // per-warp wait: only for this warp's chunk (skip own chunk)
        if (t > 0 && !own) {
            if (lane == 0) {
                int ph = s ? p1 : p0;
                unsigned done = 0;
                while (!done) {
                    asm volatile(
                        "{\n\t.reg .pred p;\n\t"
                        "mbarrier.try_wait.parity.acquire.cta.shared::cta.b64 p, [%1], %2, 0x989680;\n\t"
                        "selp.b32 %0, 1, 0, p;\n\t}"
                        : "=r"(done) : "r"(mb_c + (unsigned)s * 8u), "r"(ph) : "memory");
                }
            }
            __syncwarp();
            if (s) p1 ^= 1; else p0 ^= 1;
            // re-arm this chunk/buffer for step t+2 (once per chunk)
            if (gate == 0 && lane == 0) {
                asm volatile("mbarrier.arrive.expect_tx.shared::cta.b64 _, [%0], %1;"
                             :: "r"(mb_c + (unsigned)s * 8u), "r"(1024) : "memory");
            }
        }

        const ull* hp = hpb + s * 1024;

        // -------- gates: warp (gate, ks8) over chunk ks8, 32 kp --------
        {
            int gkp = ks8 * 32 + lane;
            ull u = (gate ? rup : zup)[gkp];
            QU A, B;
            A.q = *(const uint4*)(hp + gkp * 4);
            B.q = *(const uint4*)(hp + gkp * 4 + 2);
            ull a0 = 0, a1 = 0, a2 = 0, a3 = 0;
            fma2(a0, A.u[0], u);
            fma2(a1, A.u[1], u);
            fma2(a2, B.u[0], u);
            fma2(a3, B.u[1], u);
            U64F2 c0, c1, c2, c3;
            c0.u = a0; c1.u = a1; c2.u = a2; c3.u = a3;
            float s0 = c0.f.x + c0.f.y, s1 = c1.f.x + c1.f.y;
            float s2 = c2.f.x + c2.f.y, s3 = c3.f.x + c3.f.y;
#pragma unroll
            for (int off = 16; off >= 1; off >>= 1) {
                s0 += __shfl_xor_sync(0xffffffffu, s0, off);
                s1 += __shfl_xor_sync(0xffffffffu, s1, off);
                s2 += __shfl_xor_sync(0xffffffffu, s2, off);
                s3 += __shfl_xor_sync(0xffffffffu, s3, off);
            }
            if (lane == 0) ((float4*)zrpf)[gate * 8 + ks8] = make_float4(s0, s1, s2, s3);
        }

        // -------- main dot: warp ks over chunk ks>>1, k-pair f32x2 --------
        {
            const ull* wp = wS + ks * 1024 + jjp * 2;
            const ull* hq = hp + ks * 64;
            ull a00 = 0, a01v = 0, a02 = 0, a03 = 0;
            ull a10 = 0, a11v = 0, a12 = 0, a13 = 0;
#pragma unroll
            for (int i = 0; i < 16; i++) {
                QU Wq, Ha, Hb;
                Wq.q = *(const uint4*)(wp + i * 64);
                Ha.q = *(const uint4*)(hq + i * 4);
                Hb.q = *(const uint4*)(hq + i * 4 + 2);
                fma2(a00,  Wq.u[0], Ha.u[0]);
                fma2(a01v, Wq.u[0], Ha.u[1]);
                fma2(a02,  Wq.u[0], Hb.u[0]);
                fma2(a03,  Wq.u[0], Hb.u[1]);
                fma2(a10,  Wq.u[1], Ha.u[0]);
                fma2(a11v, Wq.u[1], Ha.u[1]);
                fma2(a12,  Wq.u[1], Hb.u[0]);
                fma2(a13,  Wq.u[1], Hb.u[1]);
            }
            U64F2 u0, u1;
            float2* pp = (float2*)part;
            u0.u = a00;  u1.u = a10;
            pp[ks * 128 + 0 * 32 + jjp] = make_float2(u0.f.x + u0.f.y, u1.f.x + u1.f.y);
            u0.u = a01v; u1.u = a11v;
            pp[ks * 128 + 1 * 32 + jjp] = make_float2(u0.f.x + u0.f.y, u1.f.x + u1.f.y);
            u0.u = a02;  u1.u = a12;
            pp[ks * 128 + 2 * 32 + jjp] = make_float2(u0.f.x + u0.f.y, u1.f.x + u1.f.y);
            u0.u = a03;  u1.u = a13;
            pp[ks * 128 + 3 * 32 + jjp] = make_float2(u0.f.x + u0.f.y, u1.f.x + u1.f.y);
        }
        __syncthreads();

        // -------- finish: reduce + gates + write + local h_new store ------
        if (tid < 256) {
            float ssum = 0.f;
#pragma unroll
            for (int ki = 0; ki < 16; ki++) ssum += part[ki * 256 + b4 * 64 + jj4];
            float gz = 0.f, gr = 0.f;
#pragma unroll
            for (int k8 = 0; k8 < 8; k8++) {
                gz += zrpf[k8 * 4 + b4];
                gr += zrpf[32 + k8 * 4 + b4];
            }
            float zt = sigmoid_fast(xzv + gz + zub);
            float rt = sigmoid_fast(xrv + gr + rub);
            float nt = tanh_fast(fmaf(ssum + hub[jj4], rt, xnv));
            U64F2 hold2; hold2.u = hp[((jjbase + jj4) >> 1) * 4 + b4];
            float hold = (jj4 & 1) ? hold2.f.y : hold2.f.x;
            float hn = (1.f - zt) * nt + zt * hold;

            out[obase] = hn;
            float hn1 = __shfl_down_sync(0xffffffffu, hn, 1);
            // write own chunk of h(t+1) directly into local buffer sf
            if ((jj4 & 1) == 0)
                hpb[sf * 1024 + ((jjbase + jj4) >> 1) * 4 + b4] = pack2(hn, hn1);

            if (t < TT - 1) {
                obase += (size_t)BB * HH;
                xnv = out[obase];
                xzv = g_xz[(t + 1) * BB + grp * 4 + b4];
                xrv = g_xr[(t + 1) * BB + grp * 4 + b4];
            } else if (tail >= BB * HH) {
                out[(size_t)TT * BB * HH + (size_t)(grp * 4 + b4) * HH + jjbase + jj4] = hn;
            }
        }
        __syncthreads();

        // -------- fan-out: 7 bulk copies (1KB) from local hpb[sf] ---------
        if (t < TT - 1 && tid < 8 && tid != rank) {
            asm volatile("fence.proxy.async.shared::cta;" ::: "memory");
            unsigned src = hpb_a + (unsigned)sf * 8192u + (unsigned)rank * 1024u;
            unsigned dst = dst_r + (unsigned)sf * 8192u;
            unsigned mb  = mb_r + (unsigned)sf * 8u;
            asm volatile(
                "cp.async.bulk.shared::cluster.shared::cta.mbarrier::complete_tx::bytes "
                "[%0], [%1], %2, [%3];"
                :: "r"(dst), "r"(src), "r"(1024u), "r"(mb) : "memory");
        }
    }

    // teardown: no CTA leaves while peers may still target its smem
    asm volatile("barrier.cluster.arrive.aligned;" ::: "memory");
    asm volatile("barrier.cluster.wait.aligned;" ::: "memory");
}

// ---------------- launch ----------------
extern "C" void kernel_launch(void* const* d_in, const int* in_sizes, int n_in,
                              void* d_out, int out_size) {
    const float* input  = (const float*)d_in[0];
    const float* hidden = (const float*)d_in[1];
    const float* zt_w_w = (const float*)d_in[2];
    const float* zt_w_b = (const float*)d_in[3];
    const float* zt_u_w = (const float*)d_in[4];
    const float* zt_u_b = (const float*)d_in[5];
    const float* rt_w_w = (const float*)d_in[6];
    const float* rt_w_b = (const float*)d_in[7];
    const float* rt_u_w = (const float*)d_in[8];
    const float* rt_u_b = (const float*)d_in[9];
    const float* h_w_w  = (const float*)d_in[10];
    const float* h_w_b  = (const float*)d_in[11];
    const float* h_u_w  = (const float*)d_in[12];
    const float* h_u_b  = (const float*)d_in[13];
    float* out = (float*)d_out;

    int tail = out_size - TT * BB * HH;

    gate_pre_kernel<<<TT * BB / 8, 256>>>(input, zt_w_w, zt_w_b, rt_w_w, rt_w_b);

    {
        dim3 grid(TT * BB / 128, HH / 64);
        xn_gemm_kernel<<<grid, 256>>>(input, h_w_w, h_w_b, out);
    }

    static int smem_set = 0;
    if (!smem_set) {
        cudaFuncSetAttribute(scan_kernel, cudaFuncAttributeMaxDynamicSharedMemorySize, SC_SMEM);
        smem_set = 1;
    }
    scan_kernel<<<128, 512, SC_SMEM>>>(hidden, zt_u_w, zt_u_b, rt_u_w, rt_u_b,
                                       h_u_w, h_u_b, out, tail);
}

// round 12
// speedup vs baseline: 1.8882x; 1.1196x over previous
#include <cuda_runtime.h>
#include <cuda_bf16.h>
#include <math.h>

// Problem dims
#define TT 512
#define BB 64
#define II 512
#define HH 512

// ---------------- device scratch ----------------
__device__ float g_xz[TT * BB];   // [t][b] includes zt_w_b
__device__ float g_xr[TT * BB];   // [t][b] includes rt_w_b

// ---------------- helpers ----------------
typedef unsigned long long ull;
union U64F2 { ull u; float2 f; };
union QU    { uint4 q; ull u[2]; };

__device__ __forceinline__ void fma2(ull& d, ull a, ull b) {
    asm("fma.rn.f32x2 %0, %1, %2, %0;" : "+l"(d) : "l"(a), "l"(b));
}
__device__ __forceinline__ ull pack2(float lo, float hi) {
    ull r; asm("mov.b64 %0, {%1, %2};" : "=l"(r) : "f"(lo), "f"(hi)); return r;
}
__device__ __forceinline__ float sigmoid_fast(float x) {
    float e, r;
    asm("ex2.approx.f32 %0, %1;" : "=f"(e) : "f"(-1.4426950408889634f * x));
    asm("rcp.approx.f32 %0, %1;" : "=f"(r) : "f"(1.0f + e));
    return r;
}
__device__ __forceinline__ float tanh_fast(float x) {
    float e, r;
    asm("ex2.approx.f32 %0, %1;" : "=f"(e) : "f"(-2.8853900817779268f * x));
    asm("rcp.approx.f32 %0, %1;" : "=f"(r) : "f"(1.0f + e));
    return fmaf(2.0f, r, -1.0f);
}
__device__ __forceinline__ unsigned smem_u32(const void* p) {
    return (unsigned)__cvta_generic_to_shared(p);
}

// ---------------- kernel 1: gate input projections xz, xr ----------------
__global__ void gate_pre_kernel(const float* __restrict__ in,
                                const float* __restrict__ zw, const float* __restrict__ zb,
                                const float* __restrict__ rw, const float* __restrict__ rb) {
    int row  = blockIdx.x * 8 + (threadIdx.x >> 5);
    int lane = threadIdx.x & 31;
    const float4* a4 = (const float4*)(in + (size_t)row * II);
    const float4* z4 = (const float4*)zw;
    const float4* r4 = (const float4*)rw;
    float az = 0.f, ar = 0.f;
#pragma unroll 4
    for (int i = lane; i < II / 4; i += 32) {
        float4 v = a4[i];
        float4 z = z4[i];
        float4 r = r4[i];
        az += v.x * z.x + v.y * z.y + v.z * z.z + v.w * z.w;
        ar += v.x * r.x + v.y * r.y + v.z * r.z + v.w * r.w;
    }
#pragma unroll
    for (int off = 16; off >= 1; off >>= 1) {
        az += __shfl_xor_sync(0xffffffffu, az, off);
        ar += __shfl_xor_sync(0xffffffffu, ar, off);
    }
    if (lane == 0) {
        g_xz[row] = az + zb[0];
        g_xr[row] = ar + rb[0];
    }
}

// ---------------- kernel 2: xn GEMM (R6, proven) ----------------
__global__ __launch_bounds__(256) void xn_gemm_kernel(const float* __restrict__ A,
                                                      const float* __restrict__ W,
                                                      const float* __restrict__ bias,
                                                      float* __restrict__ C) {
    __shared__ ull As2[16][130];
    __shared__ ull Ws2[16][66];

    int tid  = threadIdx.x;
    int ncol = tid & 7;
    int mrow = tid >> 3;
    int nc2  = ncol * 2;
    int bm   = blockIdx.x * 128;
    int bn   = blockIdx.y * 64;

    ull acc[4][8];
#pragma unroll
    for (int i = 0; i < 4; i++)
#pragma unroll
        for (int j = 0; j < 8; j++) acc[i][j] = 0ull;

    const float4* A4 = (const float4*)A;
    const float4* W4 = (const float4*)W;

    float4 pa[4], pw[2];
#pragma unroll
    for (int q = 0; q < 4; q++) {
        int s = tid + q * 256;
        pa[q] = A4[(size_t)(bm + (s >> 3)) * 128 + (s & 7)];
    }
#pragma unroll
    for (int q = 0; q < 2; q++) {
        int s = tid + q * 256;
        pw[q] = W4[(size_t)(bn + (s >> 3)) * 128 + (s & 7)];
    }

    for (int blk = 0; blk < 16; blk++) {
#pragma unroll
        for (int q = 0; q < 4; q++) {
            int s = tid + q * 256;
            int m = s >> 3, f4 = s & 7;
            As2[f4 * 2][m]     = pack2(pa[q].x, pa[q].y);
            As2[f4 * 2 + 1][m] = pack2(pa[q].z, pa[q].w);
        }
#pragma unroll
        for (int q = 0; q < 2; q++) {
            int s = tid + q * 256;
            int n = s >> 3, f4 = s & 7;
            Ws2[f4 * 2][n]     = pack2(pw[q].x, pw[q].y);
            Ws2[f4 * 2 + 1][n] = pack2(pw[q].z, pw[q].w);
        }
        __syncthreads();
        if (blk < 15) {
            int kq = (blk + 1) * 8;
#pragma unroll
            for (int q = 0; q < 4; q++) {
                int s = tid + q * 256;
                pa[q] = A4[(size_t)(bm + (s >> 3)) * 128 + kq + (s & 7)];
            }
#pragma unroll
            for (int q = 0; q < 2; q++) {
                int s = tid + q * 256;
                pw[q] = W4[(size_t)(bn + (s >> 3)) * 128 + kq + (s & 7)];
            }
        }
#pragma unroll
        for (int kp = 0; kp < 16; kp++) {
            QU a01, a23, w0, w1, w2, w3;
            a01.q = *(const uint4*)&As2[kp][mrow * 4];
            a23.q = *(const uint4*)&As2[kp][mrow * 4 + 2];
            w0.q  = *(const uint4*)&Ws2[kp][nc2];
            w1.q  = *(const uint4*)&Ws2[kp][nc2 + 16];
            w2.q  = *(const uint4*)&Ws2[kp][nc2 + 32];
            w3.q  = *(const uint4*)&Ws2[kp][nc2 + 48];
            ull av[4] = {a01.u[0], a01.u[1], a23.u[0], a23.u[1]};
            ull wv[8] = {w0.u[0], w0.u[1], w1.u[0], w1.u[1],
                         w2.u[0], w2.u[1], w3.u[0], w3.u[1]};
#pragma unroll
            for (int i = 0; i < 4; i++)
#pragma unroll
                for (int j = 0; j < 8; j++) fma2(acc[i][j], av[i], wv[j]);
        }
        __syncthreads();
    }

    float2 bq[4];
#pragma unroll
    for (int q = 0; q < 4; q++)
        bq[q] = ((const float2*)bias)[(bn >> 1) + (nc2 >> 1) + q * 8];

#pragma unroll
    for (int mi = 0; mi < 4; mi++) {
        int m = bm + mrow * 4 + mi;
#pragma unroll
        for (int q = 0; q < 4; q++) {
            U64F2 c0, c1;
            c0.u = acc[mi][q * 2];
            c1.u = acc[mi][q * 2 + 1];
            float2 o;
            o.x = c0.f.x + c0.f.y + bq[q].x;
            o.y = c1.f.x + c1.f.y + bq[q].y;
            ((float2*)C)[(size_t)m * 256 + (bn >> 1) + (nc2 >> 1) + q * 8] = o;
        }
    }
}

// ---------------- kernel 3: recurrent scan ----------------
// R11 (per-chunk mbarriers, 7x1KB bulk DSMEM sends) + HALF-W-IN-REGISTERS:
// each dot warp keeps kp 0-7 of its 16-kp segment in 16 ull registers
// (loaded once from global); kp 8-15 come from smem (wS now 64KB).
#define WS_OFF   0                        // float[128 kpc][128] = 64KB
#define HP_OFF   65536                    // ull[2][1024]  = 16KB
#define PART_OFF (HP_OFF + 16384)         // float[16][4][64] = 16KB
#define ZRP_OFF  (PART_OFF + 16384)       // float[64]
#define ZUP_OFF  (ZRP_OFF + 256)          // ull[256]
#define RUP_OFF  (ZUP_OFF + 2048)         // ull[256]
#define HUB_OFF  (RUP_OFF + 2048)         // float[64]
#define MBAR_OFF (HUB_OFF + 256)          // 16 x b64 = [chunk c][buf s]
#define SC_SMEM  (MBAR_OFF + 128)

extern __shared__ char sc_smem[];

__global__ void __cluster_dims__(8, 1, 1) __launch_bounds__(512, 1)
scan_kernel(const float* __restrict__ hidden,
            const float* __restrict__ ztu_g, const float* __restrict__ ztub,
            const float* __restrict__ rtu_g, const float* __restrict__ rtub,
            const float* __restrict__ huw, const float* __restrict__ hub_g,
            float* __restrict__ out, int tail) {
    ull*   wS   = (ull*)(sc_smem + WS_OFF);
    ull*   hpb  = (ull*)(sc_smem + HP_OFF);
    float* part = (float*)(sc_smem + PART_OFF);
    float* zrpf = (float*)(sc_smem + ZRP_OFF);
    ull*   zup  = (ull*)(sc_smem + ZUP_OFF);
    ull*   rup  = (ull*)(sc_smem + RUP_OFF);
    float* hub  = (float*)(sc_smem + HUB_OFF);

    int tid    = threadIdx.x;
    int rank   = blockIdx.x & 7;
    int grp    = blockIdx.x >> 3;
    int jjbase = rank * 64;
    unsigned mbase = smem_u32(sc_smem + MBAR_OFF);
    unsigned hpb_a = smem_u32(hpb);

    int lane = tid & 31;
    int warp = tid >> 5;
    int jjp  = lane;            // jj pair 0..31
    int ks   = warp;            // k segment 0..15 (16 kp each)
    int gate = warp & 1;
    int ks8  = warp >> 1;
    int chnk = warp >> 1;       // the ONLY h-chunk this warp reads
    int own  = (chnk == rank);
    int jj4  = tid & 63;
    int b4   = (tid >> 6) & 3;

    // -------- prologue --------
    // smem half of W: kp-local 8..15 of each segment, compressed index
    for (int i = tid; i < 64 * 512; i += 512) {
        int jj = i >> 9, k = i & 511;
        int kp = k >> 1, kpl = kp & 15;
        if (kpl >= 8) {
            int kpc = (kp >> 4) * 8 + (kpl - 8);
            ((float*)wS)[kpc * 128 + jj * 2 + (k & 1)] = huw[(size_t)(jjbase + jj) * HH + k];
        }
    }
    // register half of W: kp-local 0..7 of this warp's segment, 2 jj rows
    ull wreg[16];
    {
        const float* wr0 = huw + (size_t)(jjbase + 2 * jjp) * HH + ks * 32;
        const float* wr1 = wr0 + HH;
#pragma unroll
        for (int i = 0; i < 8; i++) {
            wreg[2 * i]     = *(const ull*)(wr0 + 2 * i);
            wreg[2 * i + 1] = *(const ull*)(wr1 + 2 * i);
        }
    }
    if (tid < 256) zup[tid] = ((const ull*)ztu_g)[tid];
    else           rup[tid - 256] = ((const ull*)rtu_g)[tid - 256];
    for (int i = tid; i < 1024; i += 512) {
        hpb[i] = ((const ull*)hidden)[(size_t)(grp * 4 + (i & 3)) * 256 + (i >> 2)];
    }
    if (tid < 64) hub[tid] = hub_g[jjbase + tid];
    float zub = ztub[0], rub = rtub[0];
    if (tid == 0) {
#pragma unroll
        for (int m = 0; m < 16; m++) {
            asm volatile("mbarrier.init.shared.b64 [%0], %1;"
                         :: "r"(mbase + m * 8), "r"(1) : "memory");
        }
#pragma unroll
        for (int m = 0; m < 16; m++) {
            asm volatile("mbarrier.arrive.expect_tx.shared::cta.b64 _, [%0], %1;"
                         :: "r"(mbase + m * 8), "r"(1024) : "memory");
        }
    }

    // per-lane remote targets (lanes/tids 0..7 -> peer ranks)
    unsigned dst_r = 0, mb_r = 0;
    if (tid < 8) {
        unsigned rem;
        asm("mapa.shared::cluster.u32 %0, %1, %2;" : "=r"(rem) : "r"(hpb_a), "r"(tid));
        dst_r = rem + (unsigned)rank * 1024u;            // our chunk slot in peer
        asm("mapa.shared::cluster.u32 %0, %1, %2;" : "=r"(rem) : "r"(mbase), "r"(tid));
        mb_r = rem + (unsigned)rank * 16u;               // mbarrier[chunk=rank][s]
    }

    // prefetch step-0 inputs
    size_t obase = 0;
    float xnv = 0.f, xzv = 0.f, xrv = 0.f;
    if (tid < 256) {
        obase = (size_t)(grp * 4 + b4) * HH + jjbase + jj4;
        xnv = out[obase];
        xzv = g_xz[grp * 4 + b4];
        xrv = g_xr[grp * 4 + b4];
    }

    __syncthreads();
    // mbarrier inits/arms visible cluster-wide before any remote complete_tx
    asm volatile("barrier.cluster.arrive.aligned;" ::: "memory");
    asm volatile("barrier.cluster.wait.aligned;" ::: "memory");

    int p0 = 0, p1 = 0;           // per-warp parity for its chunk, buffers 0/1
    unsigned mb_c = mbase + (unsigned)chnk * 16u;

    for (int t = 0; t < TT; t++) {
        int s = t & 1, sf = s ^ 1;

        // per-warp wait: only for this warp's chunk (skip own chunk)
        if (t > 0 && !own) {
            if (lane == 0) {
                int ph = s ? p1 : p0;
                unsigned done = 0;
                while (!done) {
                    asm volatile(
                        "{\n\t.reg .pred p;\n\t"
                        "mbarrier.try_wait.parity.acquire.cta.shared::cta.b64 p, [%1], %2, 0x989680;\n\t"
                        "selp.b32 %0, 1, 0, p;\n\t}"
                        : "=r"(done) : "r"(mb_c + (unsigned)s * 8u), "r"(ph) : "memory");
                }
            }
            __syncwarp();
            if (s) p1 ^= 1; else p0 ^= 1;
            // re-arm this chunk/buffer for step t+2 (once per chunk)
            if (gate == 0 && lane == 0) {
                asm volatile("mbarrier.arrive.expect_tx.shared::cta.b64 _, [%0], %1;"
                             :: "r"(mb_c + (unsigned)s * 8u), "r"(1024) : "memory");
            }
        }

        const ull* hp = hpb + s * 1024;

        // -------- gates: warp (gate, ks8) over chunk ks8, 32 kp --------
        {
            int gkp = ks8 * 32 + lane;
            ull u = (gate ? rup : zup)[gkp];
            QU A, B;
            A.q = *(const uint4*)(hp + gkp * 4);
            B.q = *(const uint4*)(hp + gkp * 4 + 2);
            ull a0 = 0, a1 = 0, a2 = 0, a3 = 0;
            fma2(a0, A.u[0], u);
            fma2(a1, A.u[1], u);
            fma2(a2, B.u[0], u);
            fma2(a3, B.u[1], u);
            U64F2 c0, c1, c2, c3;
            c0.u = a0; c1.u = a1; c2.u = a2; c3.u = a3;
            float s0 = c0.f.x + c0.f.y, s1 = c1.f.x + c1.f.y;
            float s2 = c2.f.x + c2.f.y, s3 = c3.f.x + c3.f.y;
#pragma unroll
            for (int off = 16; off >= 1; off >>= 1) {
                s0 += __shfl_xor_sync(0xffffffffu, s0, off);
                s1 += __shfl_xor_sync(0xffffffffu, s1, off);
                s2 += __shfl_xor_sync(0xffffffffu, s2, off);
                s3 += __shfl_xor_sync(0xffffffffu, s3, off);
            }
            if (lane == 0) ((float4*)zrpf)[gate * 8 + ks8] = make_float4(s0, s1, s2, s3);
        }

        // -------- main dot: kp 0-7 from registers, kp 8-15 from smem ------
        {
            const ull* hq = hp + ks * 64;
            ull a00 = 0, a01v = 0, a02 = 0, a03 = 0;
            ull a10 = 0, a11v = 0, a12 = 0, a13 = 0;
#pragma unroll
            for (int i = 0; i < 8; i++) {
                QU Ha, Hb;
                Ha.q = *(const uint4*)(hq + i * 4);
                Hb.q = *(const uint4*)(hq + i * 4 + 2);
                fma2(a00,  wreg[2 * i],     Ha.u[0]);
                fma2(a01v, wreg[2 * i],     Ha.u[1]);
                fma2(a02,  wreg[2 * i],     Hb.u[0]);
                fma2(a03,  wreg[2 * i],     Hb.u[1]);
                fma2(a10,  wreg[2 * i + 1], Ha.u[0]);
                fma2(a11v, wreg[2 * i + 1], Ha.u[1]);
                fma2(a12,  wreg[2 * i + 1], Hb.u[0]);
                fma2(a13,  wreg[2 * i + 1], Hb.u[1]);
            }
#pragma unroll
            for (int i = 8; i < 16; i++) {
                QU Wq, Ha, Hb;
                Wq.q = *(const uint4*)(wS + (ks * 8 + (i - 8)) * 64 + jjp * 2);
                Ha.q = *(const uint4*)(hq + i * 4);
                Hb.q = *(const uint4*)(hq + i * 4 + 2);
                fma2(a00,  Wq.u[0], Ha.u[0]);
                fma2(a01v, Wq.u[0], Ha.u[1]);
                fma2(a02,  Wq.u[0], Hb.u[0]);
                fma2(a03,  Wq.u[0], Hb.u[1]);
                fma2(a10,  Wq.u[1], Ha.u[0]);
                fma2(a11v, Wq.u[1], Ha.u[1]);
                fma2(a12,  Wq.u[1], Hb.u[0]);
                fma2(a13,  Wq.u[1], Hb.u[1]);
            }
            U64F2 u0, u1;
            float2* pp = (float2*)part;
            u0.u = a00;  u1.u = a10;
            pp[ks * 128 + 0 * 32 + jjp] = make_float2(u0.f.x + u0.f.y, u1.f.x + u1.f.y);
            u0.u = a01v; u1.u = a11v;
            pp[ks * 128 + 1 * 32 + jjp] = make_float2(u0.f.x + u0.f.y, u1.f.x + u1.f.y);
            u0.u = a02;  u1.u = a12;
            pp[ks * 128 + 2 * 32 + jjp] = make_float2(u0.f.x + u0.f.y, u1.f.x + u1.f.y);
            u0.u = a03;  u1.u = a13;
            pp[ks * 128 + 3 * 32 + jjp] = make_float2(u0.f.x + u0.f.y, u1.f.x + u1.f.y);
        }
        __syncthreads();

        // -------- finish: reduce + gates + write + local h_new store ------
        if (tid < 256) {
            float ssum = 0.f;
#pragma unroll
            for (int ki = 0; ki < 16; ki++) ssum += part[ki * 256 + b4 * 64 + jj4];
            float gz = 0.f, gr = 0.f;
#pragma unroll
            for (int k8 = 0; k8 < 8; k8++) {
                gz += zrpf[k8 * 4 + b4];
                gr += zrpf[32 + k8 * 4 + b4];
            }
            float zt = sigmoid_fast(xzv + gz + zub);
            float rt = sigmoid_fast(xrv + gr + rub);
            float nt = tanh_fast(fmaf(ssum + hub[jj4], rt, xnv));
            U64F2 hold2; hold2.u = hp[((jjbase + jj4) >> 1) * 4 + b4];
            float hold = (jj4 & 1) ? hold2.f.y : hold2.f.x;
            float hn = (1.f - zt) * nt + zt * hold;

            out[obase] = hn;
            float hn1 = __shfl_down_sync(0xffffffffu, hn, 1);
            // write own chunk of h(t+1) directly into local buffer sf
            if ((jj4 & 1) == 0)
                hpb[sf * 1024 + ((jjbase + jj4) >> 1) * 4 + b4] = pack2(hn, hn1);

            if (t < TT - 1) {
                obase += (size_t)BB * HH;
                xnv = out[obase];
                xzv = g_xz[(t + 1) * BB + grp * 4 + b4];
                xrv = g_xr[(t + 1) * BB + grp * 4 + b4];
            } else if (tail >= BB * HH) {
                out[(size_t)TT * BB * HH + (size_t)(grp * 4 + b4) * HH + jjbase + jj4] = hn;
            }
        }
        __syncthreads();

        // -------- fan-out: 7 bulk copies (1KB) from local hpb[sf] ---------
        if (t < TT - 1 && tid < 8 && tid != rank) {
            asm volatile("fence.proxy.async.shared::cta;" ::: "memory");
            unsigned src = hpb_a + (unsigned)sf * 8192u + (unsigned)rank * 1024u;
            unsigned dst = dst_r + (unsigned)sf * 8192u;
            unsigned mb  = mb_r + (unsigned)sf * 8u;
            asm volatile(
                "cp.async.bulk.shared::cluster.shared::cta.mbarrier::complete_tx::bytes "
                "[%0], [%1], %2, [%3];"
                :: "r"(dst), "r"(src), "r"(1024u), "r"(mb) : "memory");
        }
    }

    // teardown: no CTA leaves while peers may still target its smem
    asm volatile("barrier.cluster.arrive.aligned;" ::: "memory");
    asm volatile("barrier.cluster.wait.aligned;" ::: "memory");
}

// ---------------- launch ----------------
extern "C" void kernel_launch(void* const* d_in, const int* in_sizes, int n_in,
                              void* d_out, int out_size) {
    const float* input  = (const float*)d_in[0];
    const float* hidden = (const float*)d_in[1];
    const float* zt_w_w = (const float*)d_in[2];
    const float* zt_w_b = (const float*)d_in[3];
    const float* zt_u_w = (const float*)d_in[4];
    const float* zt_u_b = (const float*)d_in[5];
    const float* rt_w_w = (const float*)d_in[6];
    const float* rt_w_b = (const float*)d_in[7];
    const float* rt_u_w = (const float*)d_in[8];
    const float* rt_u_b = (const float*)d_in[9];
    const float* h_w_w  = (const float*)d_in[10];
    const float* h_w_b  = (const float*)d_in[11];
    const float* h_u_w  = (const float*)d_in[12];
    const float* h_u_b  = (const float*)d_in[13];
    float* out = (float*)d_out;

    int tail = out_size - TT * BB * HH;

    gate_pre_kernel<<<TT * BB / 8, 256>>>(input, zt_w_w, zt_w_b, rt_w_w, rt_w_b);

    {
        dim3 grid(TT * BB / 128, HH / 64);
        xn_gemm_kernel<<<grid, 256>>>(input, h_w_w, h_w_b, out);
    }

    static int smem_set = 0;
    if (!smem_set) {
        cudaFuncSetAttribute(scan_kernel, cudaFuncAttributeMaxDynamicSharedMemorySize, SC_SMEM);
        smem_set = 1;
    }
    scan_kernel<<<128, 512, SC_SMEM>>>(hidden, zt_u_w, zt_u_b, rt_u_w, rt_u_b,
                                       h_u_w, h_u_b, out, tail);
}

// round 13
// speedup vs baseline: 1.8886x; 1.0002x over previous
#include <cuda_runtime.h>
#include <cuda_bf16.h>
#include <math.h>

// Problem dims
#define TT 512
#define BB 64
#define II 512
#define HH 512

// ---------------- device scratch ----------------
__device__ float g_xz[TT * BB];   // [t][b] includes zt_w_b
__device__ float g_xr[TT * BB];   // [t][b] includes rt_w_b

// ---------------- helpers ----------------
typedef unsigned long long ull;
union U64F2 { ull u; float2 f; };
union QU    { uint4 q; ull u[2]; };

__device__ __forceinline__ void fma2(ull& d, ull a, ull b) {
    asm("fma.rn.f32x2 %0, %1, %2, %0;" : "+l"(d) : "l"(a), "l"(b));
}
__device__ __forceinline__ ull pack2(float lo, float hi) {
    ull r; asm("mov.b64 %0, {%1, %2};" : "=l"(r) : "f"(lo), "f"(hi)); return r;
}
__device__ __forceinline__ float sigmoid_fast(float x) {
    float e, r;
    asm("ex2.approx.f32 %0, %1;" : "=f"(e) : "f"(-1.4426950408889634f * x));
    asm("rcp.approx.f32 %0, %1;" : "=f"(r) : "f"(1.0f + e));
    return r;
}
__device__ __forceinline__ float tanh_fast(float x) {
    float e, r;
    asm("ex2.approx.f32 %0, %1;" : "=f"(e) : "f"(-2.8853900817779268f * x));
    asm("rcp.approx.f32 %0, %1;" : "=f"(r) : "f"(1.0f + e));
    return fmaf(2.0f, r, -1.0f);
}
__device__ __forceinline__ unsigned smem_u32(const void* p) {
    return (unsigned)__cvta_generic_to_shared(p);
}
__device__ __forceinline__ void bar_sync(int id, int cnt) {
    asm volatile("bar.sync %0, %1;" :: "r"(id), "r"(cnt) : "memory");
}
__device__ __forceinline__ void bar_arrive(int id, int cnt) {
    asm volatile("bar.arrive %0, %1;" :: "r"(id), "r"(cnt) : "memory");
}

// ---------------- kernel 1: gate input projections xz, xr ----------------
__global__ void gate_pre_kernel(const float* __restrict__ in,
                                const float* __restrict__ zw, const float* __restrict__ zb,
                                const float* __restrict__ rw, const float* __restrict__ rb) {
    int row  = blockIdx.x * 8 + (threadIdx.x >> 5);
    int lane = threadIdx.x & 31;
    const float4* a4 = (const float4*)(in + (size_t)row * II);
    const float4* z4 = (const float4*)zw;
    const float4* r4 = (const float4*)rw;
    float az = 0.f, ar = 0.f;
#pragma unroll 4
    for (int i = lane; i < II / 4; i += 32) {
        float4 v = a4[i];
        float4 z = z4[i];
        float4 r = r4[i];
        az += v.x * z.x + v.y * z.y + v.z * z.z + v.w * z.w;
        ar += v.x * r.x + v.y * r.y + v.z * r.z + v.w * r.w;
    }
#pragma unroll
    for (int off = 16; off >= 1; off >>= 1) {
        az += __shfl_xor_sync(0xffffffffu, az, off);
        ar += __shfl_xor_sync(0xffffffffu, ar, off);
    }
    if (lane == 0) {
        g_xz[row] = az + zb[0];
        g_xr[row] = ar + rb[0];
    }
}

// ---------------- kernel 2: xn GEMM (R6, proven) ----------------
__global__ __launch_bounds__(256) void xn_gemm_kernel(const float* __restrict__ A,
                                                      const float* __restrict__ W,
                                                      const float* __restrict__ bias,
                                                      float* __restrict__ C) {
    __shared__ ull As2[16][130];
    __shared__ ull Ws2[16][66];

    int tid  = threadIdx.x;
    int ncol = tid & 7;
    int mrow = tid >> 3;
    int nc2  = ncol * 2;
    int bm   = blockIdx.x * 128;
    int bn   = blockIdx.y * 64;

    ull acc[4][8];
#pragma unroll
    for (int i = 0; i < 4; i++)
#pragma unroll
        for (int j = 0; j < 8; j++) acc[i][j] = 0ull;

    const float4* A4 = (const float4*)A;
    const float4* W4 = (const float4*)W;

    float4 pa[4], pw[2];
#pragma unroll
    for (int q = 0; q < 4; q++) {
        int s = tid + q * 256;
        pa[q] = A4[(size_t)(bm + (s >> 3)) * 128 + (s & 7)];
    }
#pragma unroll
    for (int q = 0; q < 2; q++) {
        int s = tid + q * 256;
        pw[q] = W4[(size_t)(bn + (s >> 3)) * 128 + (s & 7)];
    }

    for (int blk = 0; blk < 16; blk++) {
#pragma unroll
        for (int q = 0; q < 4; q++) {
            int s = tid + q * 256;
            int m = s >> 3, f4 = s & 7;
            As2[f4 * 2][m]     = pack2(pa[q].x, pa[q].y);
            As2[f4 * 2 + 1][m] = pack2(pa[q].z, pa[q].w);
        }
#pragma unroll
        for (int q = 0; q < 2; q++) {
            int s = tid + q * 256;
            int n = s >> 3, f4 = s & 7;
            Ws2[f4 * 2][n]     = pack2(pw[q].x, pw[q].y);
            Ws2[f4 * 2 + 1][n] = pack2(pw[q].z, pw[q].w);
        }
        __syncthreads();
        if (blk < 15) {
            int kq = (blk + 1) * 8;
#pragma unroll
            for (int q = 0; q < 4; q++) {
                int s = tid + q * 256;
                pa[q] = A4[(size_t)(bm + (s >> 3)) * 128 + kq + (s & 7)];
            }
#pragma unroll
            for (int q = 0; q < 2; q++) {
                int s = tid + q * 256;
                pw[q] = W4[(size_t)(bn + (s >> 3)) * 128 + kq + (s & 7)];
            }
        }
#pragma unroll
        for (int kp = 0; kp < 16; kp++) {
            QU a01, a23, w0, w1, w2, w3;
            a01.q = *(const uint4*)&As2[kp][mrow * 4];
            a23.q = *(const uint4*)&As2[kp][mrow * 4 + 2];
            w0.q  = *(const uint4*)&Ws2[kp][nc2];
            w1.q  = *(const uint4*)&Ws2[kp][nc2 + 16];
            w2.q  = *(const uint4*)&Ws2[kp][nc2 + 32];
            w3.q  = *(const uint4*)&Ws2[kp][nc2 + 48];
            ull av[4] = {a01.u[0], a01.u[1], a23.u[0], a23.u[1]};
            ull wv[8] = {w0.u[0], w0.u[1], w1.u[0], w1.u[1],
                         w2.u[0], w2.u[1], w3.u[0], w3.u[1]};
#pragma unroll
            for (int i = 0; i < 4; i++)
#pragma unroll
                for (int j = 0; j < 8; j++) fma2(acc[i][j], av[i], wv[j]);
        }
        __syncthreads();
    }

    float2 bq[4];
#pragma unroll
    for (int q = 0; q < 4; q++)
        bq[q] = ((const float2*)bias)[(bn >> 1) + (nc2 >> 1) + q * 8];

#pragma unroll
    for (int mi = 0; mi < 4; mi++) {
        int m = bm + mrow * 4 + mi;
#pragma unroll
        for (int q = 0; q < 4; q++) {
            U64F2 c0, c1;
            c0.u = acc[mi][q * 2];
            c1.u = acc[mi][q * 2 + 1];
            float2 o;
            o.x = c0.f.x + c0.f.y + bq[q].x;
            o.y = c1.f.x + c1.f.y + bq[q].y;
            ((float2*)C)[(size_t)m * 256 + (bn >> 1) + (nc2 >> 1) + q * 8] = o;
        }
    }
}

// ---------------- kernel 3: recurrent scan ----------------
// R12 + warp-group decoupling: part/zrpf double-buffered; post-dot sync is
// bar.arrive (warps 8-15) / bar.sync (warps 0-7) on parity-alternating ids;
// post-phase4 sync is a named barrier over warps 0-7 (+ own-chunk warps when
// rank>=4). Warps 8-15 run ahead to their next chunk wait.
#define WS_OFF   0                        // float[128 kpc][128] = 64KB
#define HP_OFF   65536                    // ull[2][1024]  = 16KB
#define PART_OFF (HP_OFF + 16384)         // float[2][16][256] = 32KB
#define ZRP_OFF  (PART_OFF + 32768)       // float[2][64] = 512
#define ZUP_OFF  (ZRP_OFF + 512)          // ull[256]
#define RUP_OFF  (ZUP_OFF + 2048)         // ull[256]
#define HUB_OFF  (RUP_OFF + 2048)         // float[64]
#define MBAR_OFF (HUB_OFF + 256)          // 16 x b64 = [chunk c][buf s]
#define SC_SMEM  (MBAR_OFF + 128)

extern __shared__ char sc_smem[];

__global__ void __cluster_dims__(8, 1, 1) __launch_bounds__(512, 1)
scan_kernel(const float* __restrict__ hidden,
            const float* __restrict__ ztu_g, const float* __restrict__ ztub,
            const float* __restrict__ rtu_g, const float* __restrict__ rtub,
            const float* __restrict__ huw, const float* __restrict__ hub_g,
            float* __restrict__ out, int tail) {
    ull*   wS   = (ull*)(sc_smem + WS_OFF);
    ull*   hpb  = (ull*)(sc_smem + HP_OFF);
    float* part = (float*)(sc_smem + PART_OFF);   // [2][4096]
    float* zrpf = (float*)(sc_smem + ZRP_OFF);    // [2][64]
    ull*   zup  = (ull*)(sc_smem + ZUP_OFF);
    ull*   rup  = (ull*)(sc_smem + RUP_OFF);
    float* hub  = (float*)(sc_smem + HUB_OFF);

    int tid    = threadIdx.x;
    int rank   = blockIdx.x & 7;
    int grp    = blockIdx.x >> 3;
    int jjbase = rank * 64;
    unsigned mbase = smem_u32(sc_smem + MBAR_OFF);
    unsigned hpb_a = smem_u32(hpb);

    int lane = tid & 31;
    int warp = tid >> 5;
    int jjp  = lane;            // jj pair 0..31
    int ks   = warp;            // k segment 0..15 (16 kp each)
    int gate = warp & 1;
    int ks8  = warp >> 1;
    int chnk = warp >> 1;       // the ONLY h-chunk this warp reads
    int own  = (chnk == rank);
    int jj4  = tid & 63;
    int b4   = (tid >> 6) & 3;
    int b1cnt = (rank >= 4) ? 320 : 256;   // warps 0-7 (+2 own warps if in 8-15)
    int inB1  = (warp < 8) || own;

    // -------- prologue --------
    // smem half of W: kp-local 8..15 of each segment, compressed index
    for (int i = tid; i < 64 * 512; i += 512) {
        int jj = i >> 9, k = i & 511;
        int kp = k >> 1, kpl = kp & 15;
        if (kpl >= 8) {
            int kpc = (kp >> 4) * 8 + (kpl - 8);
            ((float*)wS)[kpc * 128 + jj * 2 + (k & 1)] = huw[(size_t)(jjbase + jj) * HH + k];
        }
    }
    // register half of W: kp-local 0..7 of this warp's segment, 2 jj rows
    ull wreg[16];
    {
        const float* wr0 = huw + (size_t)(jjbase + 2 * jjp) * HH + ks * 32;
        const float* wr1 = wr0 + HH;
#pragma unroll
        for (int i = 0; i < 8; i++) {
            wreg[2 * i]     = *(const ull*)(wr0 + 2 * i);
            wreg[2 * i + 1] = *(const ull*)(wr1 + 2 * i);
        }
    }
    if (tid < 256) zup[tid] = ((const ull*)ztu_g)[tid];
    else           rup[tid - 256] = ((const ull*)rtu_g)[tid - 256];
    for (int i = tid; i < 1024; i += 512) {
        hpb[i] = ((const ull*)hidden)[(size_t)(grp * 4 + (i & 3)) * 256 + (i >> 2)];
    }
    if (tid < 64) hub[tid] = hub_g[jjbase + tid];
    float zub = ztub[0], rub = rtub[0];
    if (tid == 0) {
#pragma unroll
        for (int m = 0; m < 16; m++) {
            asm volatile("mbarrier.init.shared.b64 [%0], %1;"
                         :: "r"(mbase + m * 8), "r"(1) : "memory");
        }
#pragma unroll
        for (int m = 0; m < 16; m++) {
            asm volatile("mbarrier.arrive.expect_tx.shared::cta.b64 _, [%0], %1;"
                         :: "r"(mbase + m * 8), "r"(1024) : "memory");
        }
    }

    // per-lane remote targets (lanes/tids 0..7 -> peer ranks)
    unsigned dst_r = 0, mb_r = 0;
    if (tid < 8) {
        unsigned rem;
        asm("mapa.shared::cluster.u32 %0, %1, %2;" : "=r"(rem) : "r"(hpb_a), "r"(tid));
        dst_r = rem + (unsigned)rank * 1024u;            // our chunk slot in peer
        asm("mapa.shared::cluster.u32 %0, %1, %2;" : "=r"(rem) : "r"(mbase), "r"(tid));
        mb_r = rem + (unsigned)rank * 16u;               // mbarrier[chunk=rank][s]
    }

    // prefetch step-0 inputs
    size_t obase = 0;
    float xnv = 0.f, xzv = 0.f, xrv = 0.f;
    if (tid < 256) {
        obase = (size_t)(grp * 4 + b4) * HH + jjbase + jj4;
        xnv = out[obase];
        xzv = g_xz[grp * 4 + b4];
        xrv = g_xr[grp * 4 + b4];
    }

    __syncthreads();
    // mbarrier inits/arms visible cluster-wide before any remote complete_tx
    asm volatile("barrier.cluster.arrive.aligned;" ::: "memory");
    asm volatile("barrier.cluster.wait.aligned;" ::: "memory");

    int p0 = 0, p1 = 0;           // per-warp parity for its chunk, buffers 0/1
    unsigned mb_c = mbase + (unsigned)chnk * 16u;

    for (int t = 0; t < TT; t++) {
        int s = t & 1, sf = s ^ 1;

        // per-warp wait for this step's chunk
        if (t > 0) {
            if (own) {
                // own chunk written by phase4 (warps 0-7). Warps 0-7 already
                // synced bar1 at end of prev step; own warps in 8-15 sync here.
                if (warp >= 8) bar_sync(1, b1cnt);
            } else {
                if (lane == 0) {
                    int ph = s ? p1 : p0;
                    unsigned done = 0;
                    while (!done) {
                        asm volatile(
                            "{\n\t.reg .pred p;\n\t"
                            "mbarrier.try_wait.parity.acquire.cta.shared::cta.b64 p, [%1], %2, 0x989680;\n\t"
                            "selp.b32 %0, 1, 0, p;\n\t}"
                            : "=r"(done) : "r"(mb_c + (unsigned)s * 8u), "r"(ph) : "memory");
                    }
                }
                __syncwarp();
                if (s) p1 ^= 1; else p0 ^= 1;
                // re-arm this chunk/buffer for step t+2 (once per chunk)
                if (gate == 0 && lane == 0) {
                    asm volatile("mbarrier.arrive.expect_tx.shared::cta.b64 _, [%0], %1;"
                                 :: "r"(mb_c + (unsigned)s * 8u), "r"(1024) : "memory");
                }
            }
        }

        const ull* hp = hpb + s * 1024;

        // -------- gates: warp (gate, ks8) over chunk ks8, 32 kp --------
        {
            int gkp = ks8 * 32 + lane;
            ull u = (gate ? rup : zup)[gkp];
            QU A, B;
            A.q = *(const uint4*)(hp + gkp * 4);
            B.q = *(const uint4*)(hp + gkp * 4 + 2);
            ull a0 = 0, a1 = 0, a2 = 0, a3 = 0;
            fma2(a0, A.u[0], u);
            fma2(a1, A.u[1], u);
            fma2(a2, B.u[0], u);
            fma2(a3, B.u[1], u);
            U64F2 c0, c1, c2, c3;
            c0.u = a0; c1.u = a1; c2.u = a2; c3.u = a3;
            float s0 = c0.f.x + c0.f.y, s1 = c1.f.x + c1.f.y;
            float s2 = c2.f.x + c2.f.y, s3 = c3.f.x + c3.f.y;
#pragma unroll
            for (int off = 16; off >= 1; off >>= 1) {
                s0 += __shfl_xor_sync(0xffffffffu, s0, off);
                s1 += __shfl_xor_sync(0xffffffffu, s1, off);
                s2 += __shfl_xor_sync(0xffffffffu, s2, off);
                s3 += __shfl_xor_sync(0xffffffffu, s3, off);
            }
            if (lane == 0)
                ((float4*)(zrpf + s * 64))[gate * 8 + ks8] = make_float4(s0, s1, s2, s3);
        }

        // -------- main dot: kp 0-7 from registers, kp 8-15 from smem ------
        {
            const ull* hq = hp + ks * 64;
            ull a00 = 0, a01v = 0, a02 = 0, a03 = 0;
            ull a10 = 0, a11v = 0, a12 = 0, a13 = 0;
#pragma unroll
            for (int i = 0; i < 8; i++) {
                QU Ha, Hb;
                Ha.q = *(const uint4*)(hq + i * 4);
                Hb.q = *(const uint4*)(hq + i * 4 + 2);
                fma2(a00,  wreg[2 * i],     Ha.u[0]);
                fma2(a01v, wreg[2 * i],     Ha.u[1]);
                fma2(a02,  wreg[2 * i],     Hb.u[0]);
                fma2(a03,  wreg[2 * i],     Hb.u[1]);
                fma2(a10,  wreg[2 * i + 1], Ha.u[0]);
                fma2(a11v, wreg[2 * i + 1], Ha.u[1]);
                fma2(a12,  wreg[2 * i + 1], Hb.u[0]);
                fma2(a13,  wreg[2 * i + 1], Hb.u[1]);
            }
#pragma unroll
            for (int i = 8; i < 16; i++) {
                QU Wq, Ha, Hb;
                Wq.q = *(const uint4*)(wS + (ks * 8 + (i - 8)) * 64 + jjp * 2);
                Ha.q = *(const uint4*)(hq + i * 4);
                Hb.q = *(const uint4*)(hq + i * 4 + 2);
                fma2(a00,  Wq.u[0], Ha.u[0]);
                fma2(a01v, Wq.u[0], Ha.u[1]);
                fma2(a02,  Wq.u[0], Hb.u[0]);
                fma2(a03,  Wq.u[0], Hb.u[1]);
                fma2(a10,  Wq.u[1], Ha.u[0]);
                fma2(a11v, Wq.u[1], Ha.u[1]);
                fma2(a12,  Wq.u[1], Hb.u[0]);
                fma2(a13,  Wq.u[1], Hb.u[1]);
            }
            U64F2 u0, u1;
            float2* pp = (float2*)(part + s * 4096);
            u0.u = a00;  u1.u = a10;
            pp[ks * 128 + 0 * 32 + jjp] = make_float2(u0.f.x + u0.f.y, u1.f.x + u1.f.y);
            u0.u = a01v; u1.u = a11v;
            pp[ks * 128 + 1 * 32 + jjp] = make_float2(u0.f.x + u0.f.y, u1.f.x + u1.f.y);
            u0.u = a02;  u1.u = a12;
            pp[ks * 128 + 2 * 32 + jjp] = make_float2(u0.f.x + u0.f.y, u1.f.x + u1.f.y);
            u0.u = a03;  u1.u = a13;
            pp[ks * 128 + 3 * 32 + jjp] = make_float2(u0.f.x + u0.f.y, u1.f.x + u1.f.y);
        }

        // post-dot: consumers (warps 0-7) block; producers 8-15 just arrive
        if (warp < 8) bar_sync(2 + s, 512);
        else          bar_arrive(2 + s, 512);

        // -------- finish (warps 0-7): reduce + gates + write + h_new ------
        if (tid < 256) {
            const float* ps = part + s * 4096;
            float ssum = 0.f;
#pragma unroll
            for (int ki = 0; ki < 16; ki++) ssum += ps[ki * 256 + b4 * 64 + jj4];
            const float* zs = zrpf + s * 64;
            float gz = 0.f, gr = 0.f;
#pragma unroll
            for (int k8 = 0; k8 < 8; k8++) {
                gz += zs[k8 * 4 + b4];
                gr += zs[32 + k8 * 4 + b4];
            }
            float zt = sigmoid_fast(xzv + gz + zub);
            float rt = sigmoid_fast(xrv + gr + rub);
            float nt = tanh_fast(fmaf(ssum + hub[jj4], rt, xnv));
            U64F2 hold2; hold2.u = hp[((jjbase + jj4) >> 1) * 4 + b4];
            float hold = (jj4 & 1) ? hold2.f.y : hold2.f.x;
            float hn = (1.f - zt) * nt + zt * hold;

            out[obase] = hn;
            float hn1 = __shfl_down_sync(0xffffffffu, hn, 1);
            // write own chunk of h(t+1) directly into local buffer sf
            if ((jj4 & 1) == 0)
                hpb[sf * 1024 + ((jjbase + jj4) >> 1) * 4 + b4] = pack2(hn, hn1);

            if (t < TT - 1) {
                obase += (size_t)BB * HH;
                xnv = out[obase];
                xzv = g_xz[(t + 1) * BB + grp * 4 + b4];
                xrv = g_xr[(t + 1) * BB + grp * 4 + b4];
            } else if (tail >= BB * HH) {
                out[(size_t)TT * BB * HH + (size_t)(grp * 4 + b4) * HH + jjbase + jj4] = hn;
            }
        }

        // post-phase4 barrier (warps 0-7 only) + fan-out sends
        if (t < TT - 1 && warp < 8) {
            bar_sync(1, b1cnt);
            if (tid < 8 && tid != rank) {
                asm volatile("fence.proxy.async.shared::cta;" ::: "memory");
                unsigned src = hpb_a + (unsigned)sf * 8192u + (unsigned)rank * 1024u;
                unsigned dst = dst_r + (unsigned)sf * 8192u;
                unsigned mb  = mb_r + (unsigned)sf * 8u;
                asm volatile(
                    "cp.async.bulk.shared::cluster.shared::cta.mbarrier::complete_tx::bytes "
                    "[%0], [%1], %2, [%3];"
                    :: "r"(dst), "r"(src), "r"(1024u), "r"(mb) : "memory");
            }
        }
    }

    // teardown: no CTA leaves while peers may still target its smem
    asm volatile("barrier.cluster.arrive.aligned;" ::: "memory");
    asm volatile("barrier.cluster.wait.aligned;" ::: "memory");
}

// ---------------- launch ----------------
extern "C" void kernel_launch(void* const* d_in, const int* in_sizes, int n_in,
                              void* d_out, int out_size) {
    const float* input  = (const float*)d_in[0];
    const float* hidden = (const float*)d_in[1];
    const float* zt_w_w = (const float*)d_in[2];
    const float* zt_w_b = (const float*)d_in[3];
    const float* zt_u_w = (const float*)d_in[4];
    const float* zt_u_b = (const float*)d_in[5];
    const float* rt_w_w = (const float*)d_in[6];
    const float* rt_w_b = (const float*)d_in[7];
    const float* rt_u_w = (const float*)d_in[8];
    const float* rt_u_b = (const float*)d_in[9];
    const float* h_w_w  = (const float*)d_in[10];
    const float* h_w_b  = (const float*)d_in[11];
    const float* h_u_w  = (const float*)d_in[12];
    const float* h_u_b  = (const float*)d_in[13];
    float* out = (float*)d_out;

    int tail = out_size - TT * BB * HH;

    gate_pre_kernel<<<TT * BB / 8, 256>>>(input, zt_w_w, zt_w_b, rt_w_w, rt_w_b);

    {
        dim3 grid(TT * BB / 128, HH / 64);
        xn_gemm_kernel<<<grid, 256>>>(input, h_w_w, h_w_b, out);
    }

    static int smem_set = 0;
    if (!smem_set) {
        cudaFuncSetAttribute(scan_kernel, cudaFuncAttributeMaxDynamicSharedMemorySize, SC_SMEM);
        smem_set = 1;
    }
    scan_kernel<<<128, 512, SC_SMEM>>>(hidden, zt_u_w, zt_u_b, rt_u_w, rt_u_b,
                                       h_u_w, h_u_b, out, tail);
}

// round 15
// speedup vs baseline: 2.1270x; 1.1262x over previous
#include <cuda_runtime.h>
#include <cuda_bf16.h>
#include <math.h>

// Problem dims
#define TT 512
#define BB 64
#define II 512
#define HH 512

// ---------------- device scratch ----------------
__device__ float g_xz[TT * BB];   // [t][b] includes zt_w_b
__device__ float g_xr[TT * BB];   // [t][b] includes rt_w_b

// ---------------- helpers ----------------
typedef unsigned long long ull;
union U64F2 { ull u; float2 f; };
union QU    { uint4 q; ull u[2]; };

__device__ __forceinline__ void fma2(ull& d, ull a, ull b) {
    asm("fma.rn.f32x2 %0, %1, %2, %0;" : "+l"(d) : "l"(a), "l"(b));
}
__device__ __forceinline__ ull pack2(float lo, float hi) {
    ull r; asm("mov.b64 %0, {%1, %2};" : "=l"(r) : "f"(lo), "f"(hi)); return r;
}
__device__ __forceinline__ float sigmoid_fast(float x) {
    float e, r;
    asm("ex2.approx.f32 %0, %1;" : "=f"(e) : "f"(-1.4426950408889634f * x));
    asm("rcp.approx.f32 %0, %1;" : "=f"(r) : "f"(1.0f + e));
    return r;
}
__device__ __forceinline__ float tanh_fast(float x) {
    float e, r;
    asm("ex2.approx.f32 %0, %1;" : "=f"(e) : "f"(-2.8853900817779268f * x));
    asm("rcp.approx.f32 %0, %1;" : "=f"(r) : "f"(1.0f + e));
    return fmaf(2.0f, r, -1.0f);
}
__device__ __forceinline__ unsigned smem_u32(const void* p) {
    return (unsigned)__cvta_generic_to_shared(p);
}
__device__ __forceinline__ void bar_sync(int id, int cnt) {
    asm volatile("bar.sync %0, %1;" :: "r"(id), "r"(cnt) : "memory");
}
__device__ __forceinline__ void bar_arrive(int id, int cnt) {
    asm volatile("bar.arrive %0, %1;" :: "r"(id), "r"(cnt) : "memory");
}
// pack two fp32 -> bf16x2; lower half = first arg (element k), upper = second (k+1)
__device__ __forceinline__ unsigned pack_bf16x2(float v_lo, float v_hi) {
    unsigned r;
    asm("cvt.rn.bf16x2.f32 %0, %1, %2;" : "=r"(r) : "f"(v_hi), "f"(v_lo));
    return r;
}

// ---------------- kernel 1: gate input projections xz, xr ----------------
__global__ void gate_pre_kernel(const float* __restrict__ in,
                                const float* __restrict__ zw, const float* __restrict__ zb,
                                const float* __restrict__ rw, const float* __restrict__ rb) {
    int row  = blockIdx.x * 8 + (threadIdx.x >> 5);
    int lane = threadIdx.x & 31;
    const float4* a4 = (const float4*)(in + (size_t)row * II);
    const float4* z4 = (const float4*)zw;
    const float4* r4 = (const float4*)rw;
    float az = 0.f, ar = 0.f;
#pragma unroll 4
    for (int i = lane; i < II / 4; i += 32) {
        float4 v = a4[i];
        float4 z = z4[i];
        float4 r = r4[i];
        az += v.x * z.x + v.y * z.y + v.z * z.z + v.w * z.w;
        ar += v.x * r.x + v.y * r.y + v.z * r.z + v.w * r.w;
    }
#pragma unroll
    for (int off = 16; off >= 1; off >>= 1) {
        az += __shfl_xor_sync(0xffffffffu, az, off);
        ar += __shfl_xor_sync(0xffffffffu, ar, off);
    }
    if (lane == 0) {
        g_xz[row] = az + zb[0];
        g_xr[row] = ar + rb[0];
    }
}

// ---------------- kernel 2: xn GEMM via mma.sync bf16, split-bf16 --------
// C[m][n] = sum_k A[m,k] W[n,k] + bias[n]. x = hi+lo bf16; x*y ~ hh+hl+lh.
// BM=128, BN=64, BK=32. 256 threads = 8 warps (4m x 2n), warp tile 32x32.
// Smem rows padded to 40 halves -> conflict-free fragment loads.
#define MMA_OP(c, a, b)                                                       \
    asm volatile("mma.sync.aligned.m16n8k16.row.col.f32.bf16.bf16.f32 "       \
                 "{%0,%1,%2,%3},{%4,%5,%6,%7},{%8,%9},{%0,%1,%2,%3};"         \
                 : "+f"(c[0]), "+f"(c[1]), "+f"(c[2]), "+f"(c[3])             \
                 : "r"(a[0]), "r"(a[1]), "r"(a[2]), "r"(a[3]),                \
                   "r"(b[0]), "r"(b[1]))

__global__ __launch_bounds__(256) void xn_gemm_mma(const float* __restrict__ A,
                                                   const float* __restrict__ W,
                                                   const float* __restrict__ bias,
                                                   float* __restrict__ C) {
    __shared__ __align__(16) unsigned short sAh[128 * 40];
    __shared__ __align__(16) unsigned short sAl[128 * 40];
    __shared__ __align__(16) unsigned short sWh[64 * 40];
    __shared__ __align__(16) unsigned short sWl[64 * 40];
    __shared__ __align__(16) float sBias[64];

    int tid  = threadIdx.x;
    int lane = tid & 31;
    int warp = tid >> 5;
    int wm   = warp >> 1;           // 0..3
    int wn   = warp & 1;            // 0..1
    int bm   = blockIdx.x * 128;
    int bn   = blockIdx.y * 64;

    if (tid < 64) sBias[tid] = bias[bn + tid];

    float acc[2][4][4];
#pragma unroll
    for (int i = 0; i < 2; i++)
#pragma unroll
        for (int j = 0; j < 4; j++)
#pragma unroll
            for (int q = 0; q < 4; q++) acc[i][j][q] = 0.f;

    int r  = lane >> 2;             // 0..7
    int g2 = (lane & 3) * 2;        // 0,2,4,6

    for (int kc = 0; kc < 16; kc++) {
        __syncthreads();
        // load + convert A tile: 128 rows x 32 k (4 float4 per thread)
#pragma unroll
        for (int i = 0; i < 4; i++) {
            int slot = tid + i * 256;
            int row  = slot >> 3;
            int f4   = slot & 7;
            float4 v = *(const float4*)(A + (size_t)(bm + row) * 512 + kc * 32 + f4 * 4);
            float hx = __bfloat162float(__float2bfloat16(v.x));
            float hy = __bfloat162float(__float2bfloat16(v.y));
            float hz = __bfloat162float(__float2bfloat16(v.z));
            float hw = __bfloat162float(__float2bfloat16(v.w));
            *(unsigned*)(sAh + row * 40 + f4 * 4)     = pack_bf16x2(v.x, v.y);
            *(unsigned*)(sAh + row * 40 + f4 * 4 + 2) = pack_bf16x2(v.z, v.w);
            *(unsigned*)(sAl + row * 40 + f4 * 4)     = pack_bf16x2(v.x - hx, v.y - hy);
            *(unsigned*)(sAl + row * 40 + f4 * 4 + 2) = pack_bf16x2(v.z - hz, v.w - hw);
        }
        // load + convert W tile: 64 rows x 32 k (2 float4 per thread)
#pragma unroll
        for (int i = 0; i < 2; i++) {
            int slot = tid + i * 256;
            int row  = slot >> 3;
            int f4   = slot & 7;
            float4 v = *(const float4*)(W + (size_t)(bn + row) * 512 + kc * 32 + f4 * 4);
            float hx = __bfloat162float(__float2bfloat16(v.x));
            float hy = __bfloat162float(__float2bfloat16(v.y));
            float hz = __bfloat162float(__float2bfloat16(v.z));
            float hw = __bfloat162float(__float2bfloat16(v.w));
            *(unsigned*)(sWh + row * 40 + f4 * 4)     = pack_bf16x2(v.x, v.y);
            *(unsigned*)(sWh + row * 40 + f4 * 4 + 2) = pack_bf16x2(v.z, v.w);
            *(unsigned*)(sWl + row * 40 + f4 * 4)     = pack_bf16x2(v.x - hx, v.y - hy);
            *(unsigned*)(sWl + row * 40 + f4 * 4 + 2) = pack_bf16x2(v.z - hz, v.w - hw);
        }
        __syncthreads();

#pragma unroll
        for (int ks = 0; ks < 2; ks++) {
            int k0 = ks * 16;
            unsigned Ah[2][4], Al[2][4], Bh[4][2], Bl[4][2];
#pragma unroll
            for (int mi = 0; mi < 2; mi++) {
                int rb = wm * 32 + mi * 16;
                Ah[mi][0] = *(const unsigned*)(sAh + (rb + r) * 40 + k0 + g2);
                Ah[mi][1] = *(const unsigned*)(sAh + (rb + r + 8) * 40 + k0 + g2);
                Ah[mi][2] = *(const unsigned*)(sAh + (rb + r) * 40 + k0 + g2 + 8);
                Ah[mi][3] = *(const unsigned*)(sAh + (rb + r + 8) * 40 + k0 + g2 + 8);
                Al[mi][0] = *(const unsigned*)(sAl + (rb + r) * 40 + k0 + g2);
                Al[mi][1] = *(const unsigned*)(sAl + (rb + r + 8) * 40 + k0 + g2);
                Al[mi][2] = *(const unsigned*)(sAl + (rb + r) * 40 + k0 + g2 + 8);
                Al[mi][3] = *(const unsigned*)(sAl + (rb + r + 8) * 40 + k0 + g2 + 8);
            }
#pragma unroll
            for (int ni = 0; ni < 4; ni++) {
                int cb = wn * 32 + ni * 8 + r;
                Bh[ni][0] = *(const unsigned*)(sWh + cb * 40 + k0 + g2);
                Bh[ni][1] = *(const unsigned*)(sWh + cb * 40 + k0 + g2 + 8);
                Bl[ni][0] = *(const unsigned*)(sWl + cb * 40 + k0 + g2);
                Bl[ni][1] = *(const unsigned*)(sWl + cb * 40 + k0 + g2 + 8);
            }
#pragma unroll
            for (int mi = 0; mi < 2; mi++)
#pragma unroll
                for (int ni = 0; ni < 4; ni++) {
                    MMA_OP(acc[mi][ni], Ah[mi], Bh[ni]);
                    MMA_OP(acc[mi][ni], Ah[mi], Bl[ni]);
                    MMA_OP(acc[mi][ni], Al[mi], Bh[ni]);
                }
        }
    }

    // epilogue: C fragment -> global with bias
#pragma unroll
    for (int mi = 0; mi < 2; mi++)
#pragma unroll
        for (int ni = 0; ni < 4; ni++) {
            int row = bm + wm * 32 + mi * 16 + r;
            int cl  = wn * 32 + ni * 8 + g2;       // col within tile
            int col = bn + cl;
            float2 o0, o1;
            o0.x = acc[mi][ni][0] + sBias[cl];
            o0.y = acc[mi][ni][1] + sBias[cl + 1];
            o1.x = acc[mi][ni][2] + sBias[cl];
            o1.y = acc[mi][ni][3] + sBias[cl + 1];
            *(float2*)(C + (size_t)row * 512 + col)       = o0;
            *(float2*)(C + (size_t)(row + 8) * 512 + col) = o1;
        }
}

// ---------------- kernel 3: recurrent scan (R13 proven, unchanged) -------
#define WS_OFF   0                        // float[128 kpc][128] = 64KB
#define HP_OFF   65536                    // ull[2][1024]  = 16KB
#define PART_OFF (HP_OFF + 16384)         // float[2][16][256] = 32KB
#define ZRP_OFF  (PART_OFF + 32768)       // float[2][64] = 512
#define ZUP_OFF  (ZRP_OFF + 512)          // ull[256]
#define RUP_OFF  (ZUP_OFF + 2048)         // ull[256]
#define HUB_OFF  (RUP_OFF + 2048)         // float[64]
#define MBAR_OFF (HUB_OFF + 256)          // 16 x b64 = [chunk c][buf s]
#define SC_SMEM  (MBAR_OFF + 128)

extern __shared__ char sc_smem[];

__global__ void __cluster_dims__(8, 1, 1) __launch_bounds__(512, 1)
scan_kernel(const float* __restrict__ hidden,
            const float* __restrict__ ztu_g, const float* __restrict__ ztub,
            const float* __restrict__ rtu_g, const float* __restrict__ rtub,
            const float* __restrict__ huw, const float* __restrict__ hub_g,
            float* __restrict__ out, int tail) {
    ull*   wS   = (ull*)(sc_smem + WS_OFF);
    ull*   hpb  = (ull*)(sc_smem + HP_OFF);
    float* part = (float*)(sc_smem + PART_OFF);   // [2][4096]
    float* zrpf = (float*)(sc_smem + ZRP_OFF);    // [2][64]
    ull*   zup  = (ull*)(sc_smem + ZUP_OFF);
    ull*   rup  = (ull*)(sc_smem + RUP_OFF);
    float* hub  = (float*)(sc_smem + HUB_OFF);

    int tid    = threadIdx.x;
    int rank   = blockIdx.x & 7;
    int grp    = blockIdx.x >> 3;
    int jjbase = rank * 64;
    unsigned mbase = smem_u32(sc_smem + MBAR_OFF);
    unsigned hpb_a = smem_u32(hpb);

    int lane = tid & 31;
    int warp = tid >> 5;
    int jjp  = lane;
    int ks   = warp;
    int gate = warp & 1;
    int ks8  = warp >> 1;
    int chnk = warp >> 1;
    int own  = (chnk == rank);
    int jj4  = tid & 63;
    int b4   = (tid >> 6) & 3;
    int b1cnt = (rank >= 4) ? 320 : 256;

    // -------- prologue --------
    for (int i = tid; i < 64 * 512; i += 512) {
        int jj = i >> 9, k = i & 511;
        int kp = k >> 1, kpl = kp & 15;
        if (kpl >= 8) {
            int kpc = (kp >> 4) * 8 + (kpl - 8);
            ((float*)wS)[kpc * 128 + jj * 2 + (k & 1)] = huw[(size_t)(jjbase + jj) * HH + k];
        }
    }
    ull wreg[16];
    {
        const float* wr0 = huw + (size_t)(jjbase + 2 * jjp) * HH + ks * 32;
        const float* wr1 = wr0 + HH;
#pragma unroll
        for (int i = 0; i < 8; i++) {
            wreg[2 * i]     = *(const ull*)(wr0 + 2 * i);
            wreg[2 * i + 1] = *(const ull*)(wr1 + 2 * i);
        }
    }
    if (tid < 256) zup[tid] = ((const ull*)ztu_g)[tid];
    else           rup[tid - 256] = ((const ull*)rtu_g)[tid - 256];
    for (int i = tid; i < 1024; i += 512) {
        hpb[i] = ((const ull*)hidden)[(size_t)(grp * 4 + (i & 3)) * 256 + (i >> 2)];
    }
    if (tid < 64) hub[tid] = hub_g[jjbase + tid];
    float zub = ztub[0], rub = rtub[0];
    if (tid == 0) {
#pragma unroll
        for (int m = 0; m < 16; m++) {
            asm volatile("mbarrier.init.shared.b64 [%0], %1;"
                         :: "r"(mbase + m * 8), "r"(1) : "memory");
        }
#pragma unroll
        for (int m = 0; m < 16; m++) {
            asm volatile("mbarrier.arrive.expect_tx.shared::cta.b64 _, [%0], %1;"
                         :: "r"(mbase + m * 8), "r"(1024) : "memory");
        }
    }

    unsigned dst_r = 0, mb_r = 0;
    if (tid < 8) {
        unsigned rem;
        asm("mapa.shared::cluster.u32 %0, %1, %2;" : "=r"(rem) : "r"(hpb_a), "r"(tid));
        dst_r = rem + (unsigned)rank * 1024u;
        asm("mapa.shared::cluster.u32 %0, %1, %2;" : "=r"(rem) : "r"(mbase), "r"(tid));
        mb_r = rem + (unsigned)rank * 16u;
    }

    size_t obase = 0;
    float xnv = 0.f, xzv = 0.f, xrv = 0.f;
    if (tid < 256) {
        obase = (size_t)(grp * 4 + b4) * HH + jjbase + jj4;
        xnv = out[obase];
        xzv = g_xz[grp * 4 + b4];
        xrv = g_xr[grp * 4 + b4];
    }

    __syncthreads();
    asm volatile("barrier.cluster.arrive.aligned;" ::: "memory");
    asm volatile("barrier.cluster.wait.aligned;" ::: "memory");

    int p0 = 0, p1 = 0;
    unsigned mb_c = mbase + (unsigned)chnk * 16u;

    for (int t = 0; t < TT; t++) {
        int s = t & 1, sf = s ^ 1;

        if (t > 0) {
            if (own) {
                if (warp >= 8) bar_sync(1, b1cnt);
            } else {
                if (lane == 0) {
                    int ph = s ? p1 : p0;
                    unsigned done = 0;
                    while (!done) {
                        asm volatile(
                            "{\n\t.reg .pred p;\n\t"
                            "mbarrier.try_wait.parity.acquire.cta.shared::cta.b64 p, [%1], %2, 0x989680;\n\t"
                            "selp.b32 %0, 1, 0, p;\n\t}"
                            : "=r"(done) : "r"(mb_c + (unsigned)s * 8u), "r"(ph) : "memory");
                    }
                }
                __syncwarp();
                if (s) p1 ^= 1; else p0 ^= 1;
                if (gate == 0 && lane == 0) {
                    asm volatile("mbarrier.arrive.expect_tx.shared::cta.b64 _, [%0], %1;"
                                 :: "r"(mb_c + (unsigned)s * 8u), "r"(1024) : "memory");
                }
            }
        }

        const ull* hp = hpb + s * 1024;

        {
            int gkp = ks8 * 32 + lane;
            ull u = (gate ? rup : zup)[gkp];
            QU A, B;
            A.q = *(const uint4*)(hp + gkp * 4);
            B.q = *(const uint4*)(hp + gkp * 4 + 2);
            ull a0 = 0, a1 = 0, a2 = 0, a3 = 0;
            fma2(a0, A.u[0], u);
            fma2(a1, A.u[1], u);
            fma2(a2, B.u[0], u);
            fma2(a3, B.u[1], u);
            U64F2 c0, c1, c2, c3;
            c0.u = a0; c1.u = a1; c2.u = a2; c3.u = a3;
            float s0 = c0.f.x + c0.f.y, s1 = c1.f.x + c1.f.y;
            float s2 = c2.f.x + c2.f.y, s3 = c3.f.x + c3.f.y;
#pragma unroll
            for (int off = 16; off >= 1; off >>= 1) {
                s0 += __shfl_xor_sync(0xffffffffu, s0, off);
                s1 += __shfl_xor_sync(0xffffffffu, s1, off);
                s2 += __shfl_xor_sync(0xffffffffu, s2, off);
                s3 += __shfl_xor_sync(0xffffffffu, s3, off);
            }
            if (lane == 0)
                ((float4*)(zrpf + s * 64))[gate * 8 + ks8] = make_float4(s0, s1, s2, s3);
        }

        {
            const ull* hq = hp + ks * 64;
            ull a00 = 0, a01v = 0, a02 = 0, a03 = 0;
            ull a10 = 0, a11v = 0, a12 = 0, a13 = 0;
#pragma unroll
            for (int i = 0; i < 8; i++) {
                QU Ha, Hb;
                Ha.q = *(const uint4*)(hq + i * 4);
                Hb.q = *(const uint4*)(hq + i * 4 + 2);
                fma2(a00,  wreg[2 * i],     Ha.u[0]);
                fma2(a01v, wreg[2 * i],     Ha.u[1]);
                fma2(a02,  wreg[2 * i],     Hb.u[0]);
                fma2(a03,  wreg[2 * i],     Hb.u[1]);
                fma2(a10,  wreg[2 * i + 1], Ha.u[0]);
                fma2(a11v, wreg[2 * i + 1], Ha.u[1]);
                fma2(a12,  wreg[2 * i + 1], Hb.u[0]);
                fma2(a13,  wreg[2 * i + 1], Hb.u[1]);
            }
#pragma unroll
            for (int i = 8; i < 16; i++) {
                QU Wq, Ha, Hb;
                Wq.q = *(const uint4*)(wS + (ks * 8 + (i - 8)) * 64 + jjp * 2);
                Ha.q = *(const uint4*)(hq + i * 4);
                Hb.q = *(const uint4*)(hq + i * 4 + 2);
                fma2(a00,  Wq.u[0], Ha.u[0]);
                fma2(a01v, Wq.u[0], Ha.u[1]);
                fma2(a02,  Wq.u[0], Hb.u[0]);
                fma2(a03,  Wq.u[0], Hb.u[1]);
                fma2(a10,  Wq.u[1], Ha.u[0]);
                fma2(a11v, Wq.u[1], Ha.u[1]);
                fma2(a12,  Wq.u[1], Hb.u[0]);
                fma2(a13,  Wq.u[1], Hb.u[1]);
            }
            U64F2 u0, u1;
            float2* pp = (float2*)(part + s * 4096);
            u0.u = a00;  u1.u = a10;
            pp[ks * 128 + 0 * 32 + jjp] = make_float2(u0.f.x + u0.f.y, u1.f.x + u1.f.y);
            u0.u = a01v; u1.u = a11v;
            pp[ks * 128 + 1 * 32 + jjp] = make_float2(u0.f.x + u0.f.y, u1.f.x + u1.f.y);
            u0.u = a02;  u1.u = a12;
            pp[ks * 128 + 2 * 32 + jjp] = make_float2(u0.f.x + u0.f.y, u1.f.x + u1.f.y);
            u0.u = a03;  u1.u = a13;
            pp[ks * 128 + 3 * 32 + jjp] = make_float2(u0.f.x + u0.f.y, u1.f.x + u1.f.y);
        }

        if (warp < 8) bar_sync(2 + s, 512);
        else          bar_arrive(2 + s, 512);

        if (tid < 256) {
            const float* ps = part + s * 4096;
            float ssum = 0.f;
#pragma unroll
            for (int ki = 0; ki < 16; ki++) ssum += ps[ki * 256 + b4 * 64 + jj4];
            const float* zs = zrpf + s * 64;
            float gz = 0.f, gr = 0.f;
#pragma unroll
            for (int k8 = 0; k8 < 8; k8++) {
                gz += zs[k8 * 4 + b4];
                gr += zs[32 + k8 * 4 + b4];
            }
            float zt = sigmoid_fast(xzv + gz + zub);
            float rt = sigmoid_fast(xrv + gr + rub);
            float nt = tanh_fast(fmaf(ssum + hub[jj4], rt, xnv));
            U64F2 hold2; hold2.u = hp[((jjbase + jj4) >> 1) * 4 + b4];
            float hold = (jj4 & 1) ? hold2.f.y : hold2.f.x;
            float hn = (1.f - zt) * nt + zt * hold;

            out[obase] = hn;
            float hn1 = __shfl_down_sync(0xffffffffu, hn, 1);
            if ((jj4 & 1) == 0)
                hpb[sf * 1024 + ((jjbase + jj4) >> 1) * 4 + b4] = pack2(hn, hn1);

            if (t < TT - 1) {
                obase += (size_t)BB * HH;
                xnv = out[obase];
                xzv = g_xz[(t + 1) * BB + grp * 4 + b4];
                xrv = g_xr[(t + 1) * BB + grp * 4 + b4];
            } else if (tail >= BB * HH) {
                out[(size_t)TT * BB * HH + (size_t)(grp * 4 + b4) * HH + jjbase + jj4] = hn;
            }
        }

        if (t < TT - 1 && warp < 8) {
            bar_sync(1, b1cnt);
            if (tid < 8 && tid != rank) {
                asm volatile("fence.proxy.async.shared::cta;" ::: "memory");
                unsigned src = hpb_a + (unsigned)sf * 8192u + (unsigned)rank * 1024u;
                unsigned dst = dst_r + (unsigned)sf * 8192u;
                unsigned mb  = mb_r + (unsigned)sf * 8u;
                asm volatile(
                    "cp.async.bulk.shared::cluster.shared::cta.mbarrier::complete_tx::bytes "
                    "[%0], [%1], %2, [%3];"
                    :: "r"(dst), "r"(src), "r"(1024u), "r"(mb) : "memory");
            }
        }
    }

    asm volatile("barrier.cluster.arrive.aligned;" ::: "memory");
    asm volatile("barrier.cluster.wait.aligned;" ::: "memory");
}

// ---------------- launch ----------------
extern "C" void kernel_launch(void* const* d_in, const int* in_sizes, int n_in,
                              void* d_out, int out_size) {
    const float* input  = (const float*)d_in[0];
    const float* hidden = (const float*)d_in[1];
    const float* zt_w_w = (const float*)d_in[2];
    const float* zt_w_b = (const float*)d_in[3];
    const float* zt_u_w = (const float*)d_in[4];
    const float* zt_u_b = (const float*)d_in[5];
    const float* rt_w_w = (const float*)d_in[6];
    const float* rt_w_b = (const float*)d_in[7];
    const float* rt_u_w = (const float*)d_in[8];
    const float* rt_u_b = (const float*)d_in[9];
    const float* h_w_w  = (const float*)d_in[10];
    const float* h_w_b  = (const float*)d_in[11];
    const float* h_u_w  = (const float*)d_in[12];
    const float* h_u_b  = (const float*)d_in[13];
    float* out = (float*)d_out;

    int tail = out_size - TT * BB * HH;

    gate_pre_kernel<<<TT * BB / 8, 256>>>(input, zt_w_w, zt_w_b, rt_w_w, rt_w_b);

    {
        dim3 grid(TT * BB / 128, HH / 64);
        xn_gemm_mma<<<grid, 256>>>(input, h_w_w, h_w_b, out);
    }

    static int smem_set = 0;
    if (!smem_set) {
        cudaFuncSetAttribute(scan_kernel, cudaFuncAttributeMaxDynamicSharedMemorySize, SC_SMEM);
        smem_set = 1;
    }
    scan_kernel<<<128, 512, SC_SMEM>>>(hidden, zt_u_w, zt_u_b, rt_u_w, rt_u_b,
                                       h_u_w, h_u_b, out, tail);
}